// round 5
// baseline (speedup 1.0000x reference)
#include <cuda_runtime.h>
#include <math.h>
#include <stdint.h>

// Problem dims
#define BB 4096
#define TT 64
#define FF 256
#define HH 256
#define AA 12
#define MTOT (BB*TT)            // 262144 rows
#define G3  768

// Scratch (device globals; no cudaMalloc allowed)
__device__ float g_xg [(size_t)MTOT * G3];     // xg, later reused as t12 [M,512]
__device__ float g_lat[(size_t)MTOT * HH];
__device__ float g_t1 [(size_t)MTOT * HH];     // rounded features
__device__ float g_t2a[(size_t)MTOT * HH];
__device__ float g_t2c[(size_t)MTOT * HH];
__device__ float g_wt  [256 * 768];            // W_hh^T rounded [k][gate]
__device__ float g_wihr[768 * 256];            // W_ih rounded
__device__ float g_w1c [512 * 256];            // [Aw1; Cw1] rounded
__device__ float g_w2a [256 * 256];
__device__ float g_w2c [256 * 256];
__device__ float g_b1c [512];                  // [Ab1 | Cb1]

__device__ __forceinline__ float round_tf32(float x) {
    uint32_t r;
    asm("cvt.rna.tf32.f32 %0, %1;" : "=r"(r) : "f"(x));
    return __uint_as_float(r);
}

__device__ __forceinline__ uint32_t smem_u32(const void* p) {
    uint32_t a;
    asm("{ .reg .u64 t; cvta.to.shared.u64 t, %1; cvt.u32.u64 %0, t; }"
        : "=r"(a) : "l"(p));
    return a;
}

__device__ __forceinline__ void cp16_cg(void* dst, const void* src) {
    asm volatile("cp.async.cg.shared.global [%0], [%1], 16;"
                 :: "r"(smem_u32(dst)), "l"(src) : "memory");
}
__device__ __forceinline__ void l2_prefetch(const void* p) {
    asm volatile("prefetch.global.L2 [%0];" :: "l"(p));
}
#define CP_COMMIT()  asm volatile("cp.async.commit_group;" ::: "memory")
#define CP_WAIT1()   asm volatile("cp.async.wait_group 1;" ::: "memory")
#define CP_WAITALL() asm volatile("cp.async.wait_all;" ::: "memory")

__device__ __forceinline__ void mma_tf32(
    float& c0, float& c1, float& c2, float& c3,
    uint32_t a0, uint32_t a1, uint32_t a2, uint32_t a3,
    uint32_t b0, uint32_t b1)
{
    asm volatile(
        "mma.sync.aligned.m16n8k8.row.col.f32.tf32.tf32.f32 "
        "{%0,%1,%2,%3}, {%4,%5,%6,%7}, {%8,%9}, {%0,%1,%2,%3};"
        : "+f"(c0), "+f"(c1), "+f"(c2), "+f"(c3)
        : "r"(a0), "r"(a1), "r"(a2), "r"(a3), "r"(b0), "r"(b1));
}

// ===========================================================================
// Prep kernels
// ===========================================================================
__global__ void prep_whh(const float* __restrict__ W_hh, float* __restrict__ Wt)
{
    int idx = blockIdx.x * 256 + threadIdx.x;
    int g = idx >> 8, k = idx & 255;
    Wt[(size_t)k * 768 + g] = round_tf32(W_hh[(size_t)g * 256 + k]);
}

// One kernel: round all MLP/input weights + concat layer1 biases.
// float4 segments: wihr 49152 | w1c(A) 16384 | w1c(C) 16384 | w2a 16384 | w2c 16384
__global__ void prep_weights(
    const float4* __restrict__ Wih, const float4* __restrict__ Aw1,
    const float4* __restrict__ Cw1, const float4* __restrict__ Aw2,
    const float4* __restrict__ Cw2, const float4* __restrict__ Ab1,
    const float4* __restrict__ Cb1,
    float4* __restrict__ wihr, float4* __restrict__ w1c,
    float4* __restrict__ w2a, float4* __restrict__ w2c,
    float4* __restrict__ b1c)
{
    int i = blockIdx.x * 256 + threadIdx.x;      // 0 .. 114687
    const float4* src;
    float4* dst;
    if (i < 49152)      { src = Wih + i;            dst = wihr + i; }
    else if (i < 65536) { src = Aw1 + (i - 49152);  dst = w1c + (i - 49152); }
    else if (i < 81920) { src = Cw1 + (i - 65536);  dst = w1c + 16384 + (i - 65536); }
    else if (i < 98304) { src = Aw2 + (i - 81920);  dst = w2a + (i - 81920); }
    else                { src = Cw2 + (i - 98304);  dst = w2c + (i - 98304); }
    float4 v = *src;
    v.x = round_tf32(v.x); v.y = round_tf32(v.y);
    v.z = round_tf32(v.z); v.w = round_tf32(v.w);
    *dst = v;
    if (i < 64)               b1c[i] = Ab1[i];
    else if (i < 128)         b1c[i] = Cb1[i - 64];
}

__global__ void round_copy4(const float4* __restrict__ src, float4* __restrict__ dst)
{
    size_t i = (size_t)blockIdx.x * 256 + threadIdx.x;
    float4 v = src[i];
    v.x = round_tf32(v.x); v.y = round_tf32(v.y);
    v.z = round_tf32(v.z); v.w = round_tf32(v.w);
    dst[i] = v;
}

// ===========================================================================
// tf32 mma.sync GEMM, cp.async 2-stage, 2 CTAs/SM.
// C[M,N] = act(A[M,K] @ W[N,K]^T + bias[N]); A,W pre-rounded tf32.
// Tile 128x128x32, 256 threads (2x4 warps), warp tile 64x32.
// grid = (N/128, M/128)  -- N fastest for A reuse in L2.
// ===========================================================================
#define GBM 128
#define GBN 128
#define GBK 32
#define APITCH 36
#define STAGEF (GBM * APITCH)                 // 4608 floats (A or B)
#define GEMM_SMEM ((4 * STAGEF + GBN) * 4)    // 74240 bytes -> 2 CTAs/SM

template<bool DO_TANH, bool ROUND_OUT>
__global__ __launch_bounds__(256, 2) void gemm_mma(
    const float* __restrict__ A, const float* __restrict__ W,
    const float* __restrict__ bias, float* __restrict__ C,
    int N, int K, int lda)
{
    extern __shared__ float sm[];
    float* sBias = sm + 4 * STAGEF;

    const int tid  = threadIdx.x;
    const int lane = tid & 31;
    const int wid  = tid >> 5;
    const int wm   = wid >> 2;
    const int wn   = wid & 3;
    const int    bn = blockIdx.x * GBN;
    const size_t bm = (size_t)blockIdx.y * GBM;

    if (tid < GBN) sBias[tid] = bias[bn + tid];

    const int lrow = tid >> 1;
    const int lkq  = (tid & 1) * 16;
    const float* Ag = A + (bm + lrow) * lda + lkq;
    const float* Wg = W + ((size_t)(bn + lrow)) * K + lkq;

    float acc[4][4][4];
#pragma unroll
    for (int mt = 0; mt < 4; mt++)
#pragma unroll
        for (int nt = 0; nt < 4; nt++)
#pragma unroll
            for (int q = 0; q < 4; q++) acc[mt][nt][q] = 0.f;

    const int NK = K / GBK;

    auto stage_copy = [&](int kt) {
        float* st = sm + (kt & 1) * 2 * STAGEF;
        const float* ap = Ag + kt * GBK;
        const float* wp = Wg + kt * GBK;
        float* dA = st + lrow * APITCH + lkq;
        float* dB = st + STAGEF + lrow * APITCH + lkq;
#pragma unroll
        for (int u = 0; u < 4; u++) {
            cp16_cg(dA + 4 * u, ap + 4 * u);
            cp16_cg(dB + 4 * u, wp + 4 * u);
        }
    };

    stage_copy(0); CP_COMMIT();
    stage_copy(1); CP_COMMIT();

    for (int kt = 0; kt < NK; kt++) {
        if (kt < NK - 1) { CP_WAIT1(); } else { CP_WAITALL(); }
        __syncthreads();

        const float* bA = sm + (kt & 1) * 2 * STAGEF;
        const float* bB = bA + STAGEF;
#pragma unroll
        for (int k8 = 0; k8 < 4; k8++) {
            const int k0 = k8 * 8;
            uint32_t a[4][4];
#pragma unroll
            for (int mt = 0; mt < 4; mt++) {
                const float* p = bA + (wm * 64 + mt * 16 + (lane >> 2)) * APITCH
                               + k0 + (lane & 3);
                a[mt][0] = __float_as_uint(p[0]);
                a[mt][1] = __float_as_uint(p[8 * APITCH]);
                a[mt][2] = __float_as_uint(p[4]);
                a[mt][3] = __float_as_uint(p[8 * APITCH + 4]);
            }
            uint32_t b[4][2];
#pragma unroll
            for (int nt = 0; nt < 4; nt++) {
                const float* p = bB + (wn * 32 + nt * 8 + (lane >> 2)) * APITCH
                               + k0 + (lane & 3);
                b[nt][0] = __float_as_uint(p[0]);
                b[nt][1] = __float_as_uint(p[4]);
            }
#pragma unroll
            for (int mt = 0; mt < 4; mt++)
#pragma unroll
                for (int nt = 0; nt < 4; nt++)
                    mma_tf32(acc[mt][nt][0], acc[mt][nt][1],
                             acc[mt][nt][2], acc[mt][nt][3],
                             a[mt][0], a[mt][1], a[mt][2], a[mt][3],
                             b[nt][0], b[nt][1]);
        }
        __syncthreads();
        if (kt + 2 < NK) { stage_copy(kt + 2); CP_COMMIT(); }
    }

    // epilogue
#pragma unroll
    for (int mt = 0; mt < 4; mt++) {
        const size_t row = bm + wm * 64 + mt * 16 + (lane >> 2);
        float* c0p = C + row * N + bn + wn * 32;
        float* c1p = c0p + (size_t)8 * N;
#pragma unroll
        for (int nt = 0; nt < 4; nt++) {
            const int cc = nt * 8 + (lane & 3) * 2;
            const float bx = sBias[wn * 32 + cc];
            const float by = sBias[wn * 32 + cc + 1];
            float v0 = acc[mt][nt][0] + bx, v1 = acc[mt][nt][1] + by;
            float v2 = acc[mt][nt][2] + bx, v3 = acc[mt][nt][3] + by;
            if (DO_TANH) {
                v0 = tanhf(v0); v1 = tanhf(v1);
                v2 = tanhf(v2); v3 = tanhf(v3);
            }
            if (ROUND_OUT) {
                v0 = round_tf32(v0); v1 = round_tf32(v1);
                v2 = round_tf32(v2); v3 = round_tf32(v3);
            }
            *(float2*)(c0p + cc) = make_float2(v0, v1);
            *(float2*)(c1p + cc) = make_float2(v2, v3);
        }
    }
}

// ===========================================================================
// GRU scan: mma.sync tf32, continuous 3-stage cp.async W pipeline,
// 1 barrier per k-tile, L2 prefetch of xg[t] during the mma loop.
// RB=32 rows/block, 128 blocks, 256 threads.
// ===========================================================================
#define RB2 32
#define HF_PITCH 257
#define HT_PITCH 260
#define WS_PITCH 776
#define WS_STAGE (16 * WS_PITCH)
// smem: ws[3][16][776] | hf[32][257] | ht[32][260] | sst[32][64] | sbh[768]
#define GRU_SMEM ((3*WS_STAGE + 32*HF_PITCH + 32*HT_PITCH + 768) * 4 + 32*64*4)

__global__ __launch_bounds__(256, 1) void gru_mma(
    const float* __restrict__ xg, const float* __restrict__ h0,
    const float* __restrict__ Wt, const float* __restrict__ b_hh,
    const int* __restrict__ starts,
    float* __restrict__ lat, float* __restrict__ h_out)
{
    extern __shared__ float sm[];
    float* ws  = sm;                          // [3][16][776]
    float* hf  = ws + 3 * WS_STAGE;           // [32][257]
    float* ht  = hf + 32 * HF_PITCH;          // [32][260]
    int*   sst = (int*)(ht + 32 * HT_PITCH);  // [32][64]
    float* sbh = (float*)(sst + 32 * 64);     // [768]

    const int tid  = threadIdx.x;
    const int lane = tid & 31;
    const int w    = tid >> 5;
    const int b0   = blockIdx.x * RB2;

    for (int i = tid; i < 32 * 64; i += 256)
        sst[i] = starts[(size_t)(b0 + (i >> 6)) * TT + (i & 63)];
    for (int i = tid; i < 768; i += 256) sbh[i] = b_hh[i];
    for (int i = tid; i < 32 * 256; i += 256) {
        int r = i >> 8, c = i & 255;
        float v = h0[(size_t)(b0 + r) * 256 + c];
        if (starts[(size_t)(b0 + r) * TT]) v = 0.f;
        hf[r * HF_PITCH + c] = v;
        ht[r * HT_PITCH + c] = round_tf32(v);
    }

    const int krow = tid >> 4;        // 0..15
    const int c4   = (tid & 15) * 4;

    auto stageW = [&](int tile, int buf) {
        const float* src = Wt + (size_t)(tile * 16 + krow) * 768 + c4;
        float* dst = ws + buf * WS_STAGE + krow * WS_PITCH + c4;
#pragma unroll
        for (int u = 0; u < 12; u++)
            cp16_cg(dst + u * 64, src + u * 64);
    };

    stageW(0, 0); CP_COMMIT();
    stageW(1, 1); CP_COMMIT();

    const int KS_TOTAL = TT * 16;     // 1024
    int ks = 0;

    for (int t = 0; t < TT; t++) {
        float acc[2][12][4];
#pragma unroll
        for (int mt = 0; mt < 2; mt++)
#pragma unroll
            for (int j = 0; j < 12; j++)
#pragma unroll
                for (int q = 0; q < 4; q++) acc[mt][j][q] = 0.f;

        for (int kt = 0; kt < 16; kt++) {
            if (ks < KS_TOTAL - 1) { CP_WAIT1(); } else { CP_WAITALL(); }
            __syncthreads();   // stage ks ready; kt==0 also orders ht writes

            if (ks + 2 < KS_TOTAL) {
                stageW((ks + 2) & 15, (ks + 2) % 3);
                CP_COMMIT();
            }

            // L2 prefetch of xg[t] slice (768 lines of 128B, 48 per kt)
            if (tid < 48) {
                int li = kt * 48 + tid;
                int r = li / 24, cl = li % 24;
                l2_prefetch(xg + ((size_t)(b0 + r) * TT + t) * G3 + cl * 32);
            }

            const int buf = ks % 3;
#pragma unroll
            for (int s = 0; s < 2; s++) {
                const int kg = kt * 16 + s * 8;
                uint32_t a[2][4];
#pragma unroll
                for (int mt = 0; mt < 2; mt++) {
                    const float* p = ht + (mt * 16 + (lane >> 2)) * HT_PITCH
                                   + kg + (lane & 3);
                    a[mt][0] = __float_as_uint(p[0]);
                    a[mt][1] = __float_as_uint(p[8 * HT_PITCH]);
                    a[mt][2] = __float_as_uint(p[4]);
                    a[mt][3] = __float_as_uint(p[8 * HT_PITCH + 4]);
                }
                const float* wb = ws + buf * WS_STAGE
                                + (s * 8 + (lane & 3)) * WS_PITCH;
#pragma unroll
                for (int g = 0; g < 3; g++)
#pragma unroll
                    for (int nt = 0; nt < 4; nt++) {
                        const int col = g * 256 + w * 32 + nt * 8 + (lane >> 2);
                        uint32_t bb0 = __float_as_uint(wb[col]);
                        uint32_t bb1 = __float_as_uint(wb[4 * WS_PITCH + col]);
                        const int j = g * 4 + nt;
                        mma_tf32(acc[0][j][0], acc[0][j][1], acc[0][j][2], acc[0][j][3],
                                 a[0][0], a[0][1], a[0][2], a[0][3], bb0, bb1);
                        mma_tf32(acc[1][j][0], acc[1][j][1], acc[1][j][2], acc[1][j][3],
                                 a[1][0], a[1][1], a[1][2], a[1][3], bb0, bb1);
                    }
            }
            ks++;
        }
        __syncthreads();   // all mma reads of ht done before pointwise writes

        // pointwise GRU update
#pragma unroll
        for (int mt = 0; mt < 2; mt++)
#pragma unroll
        for (int rh = 0; rh < 2; rh++) {
            const int row  = mt * 16 + rh * 8 + (lane >> 2);
            const int grow = b0 + row;
            const size_t gbt = (size_t)grow * TT + t;
            const float* xb = xg + gbt * 768;
            float* lb = lat + gbt * 256;
            float msk = 1.f;
            if (t < TT - 1) msk = sst[row * 64 + t + 1] ? 0.f : 1.f;
#pragma unroll
            for (int nt = 0; nt < 4; nt++) {
                const int c = w * 32 + nt * 8 + (lane & 3) * 2;
                float2 xr = *(const float2*)(xb + c);
                float2 xz = *(const float2*)(xb + 256 + c);
                float2 xn = *(const float2*)(xb + 512 + c);
                const int q = rh * 2;
                float hr0 = acc[mt][nt][q]     + sbh[c];
                float hr1 = acc[mt][nt][q + 1] + sbh[c + 1];
                float hz0 = acc[mt][4 + nt][q]     + sbh[256 + c];
                float hz1 = acc[mt][4 + nt][q + 1] + sbh[256 + c + 1];
                float hn0 = acc[mt][8 + nt][q]     + sbh[512 + c];
                float hn1 = acc[mt][8 + nt][q + 1] + sbh[512 + c + 1];
                float r0 = 1.f / (1.f + __expf(-(xr.x + hr0)));
                float r1 = 1.f / (1.f + __expf(-(xr.y + hr1)));
                float z0 = 1.f / (1.f + __expf(-(xz.x + hz0)));
                float z1 = 1.f / (1.f + __expf(-(xz.y + hz1)));
                float n0 = tanhf(xn.x + r0 * hn0);
                float n1 = tanhf(xn.y + r1 * hn1);
                float ho0 = hf[row * HF_PITCH + c];
                float ho1 = hf[row * HF_PITCH + c + 1];
                float v0 = (1.f - z0) * n0 + z0 * ho0;
                float v1 = (1.f - z1) * n1 + z1 * ho1;
                *(float2*)(lb + c) = make_float2(round_tf32(v0), round_tf32(v1));
                if (t == TT - 1) {
                    *(float2*)(h_out + (size_t)grow * 256 + c) = make_float2(v0, v1);
                } else {
                    float m0 = v0 * msk, m1 = v1 * msk;
                    hf[row * HF_PITCH + c]     = m0;
                    hf[row * HF_PITCH + c + 1] = m1;
                    ht[row * HT_PITCH + c]     = round_tf32(m0);
                    ht[row * HT_PITCH + c + 1] = round_tf32(m1);
                }
            }
        }
        // next t's kt=0 barrier orders these writes vs mma reads
    }
}

// ---------------------------------------------------------------------------
// Heads
// ---------------------------------------------------------------------------
__global__ __launch_bounds__(256) void head_kernel(
    const float* __restrict__ t2a, const float* __restrict__ t2c,
    const float* __restrict__ Aw3, const float* __restrict__ Ab3,
    const float* __restrict__ Cw3, const float* __restrict__ Cb3,
    float* __restrict__ out)
{
    __shared__ float wa[12][256];
    __shared__ float wc[256];
    __shared__ float ba[12];
    __shared__ float bc;

    const int tid = threadIdx.x;
    for (int i = tid; i < 12 * 256; i += 256) wa[i >> 8][i & 255] = Aw3[i];
    if (tid < 256) wc[tid] = Cw3[tid];
    if (tid < 12)  ba[tid] = Ab3[tid];
    if (tid == 0)  bc = Cb3[0];
    __syncthreads();

    const int warp = tid >> 5;
    const int lane = tid & 31;
    const size_t row = (size_t)blockIdx.x * 8 + warp;

    const float* ra = t2a + row * 256;
    const float* rc = t2c + row * 256;
    float va[8], vc[8];
#pragma unroll
    for (int u = 0; u < 8; u++) {
        va[u] = ra[lane + 32 * u];
        vc[u] = rc[lane + 32 * u];
    }

    float s[13];
#pragma unroll
    for (int a = 0; a < 12; a++) {
        float acc = 0.f;
#pragma unroll
        for (int u = 0; u < 8; u++) acc = fmaf(va[u], wa[a][lane + 32 * u], acc);
        s[a] = acc;
    }
    {
        float acc = 0.f;
#pragma unroll
        for (int u = 0; u < 8; u++) acc = fmaf(vc[u], wc[lane + 32 * u], acc);
        s[12] = acc;
    }
#pragma unroll
    for (int a = 0; a < 13; a++)
#pragma unroll
        for (int o = 16; o > 0; o >>= 1)
            s[a] += __shfl_xor_sync(0xffffffffu, s[a], o);
    if (lane == 0) {
        float* o = out + row * 13;
#pragma unroll
        for (int a = 0; a < 12; a++) o[a] = s[a] + ba[a];
        o[12] = s[12] + bc;
    }
}

__global__ void std_kernel(const float* __restrict__ log_std, float* __restrict__ out)
{
    int a = threadIdx.x;
    if (a < AA) {
        float v = log_std[a];
        v = fminf(fmaxf(v, -2.0f), -0.5f);
        out[a] = __expf(v);
    }
}

// ---------------------------------------------------------------------------
extern "C" void kernel_launch(void* const* d_in, const int* in_sizes, int n_in,
                              void* d_out, int out_size)
{
    const float* features = (const float*)d_in[0];
    const float* hidden   = (const float*)d_in[1];
    const float* W_ih     = (const float*)d_in[2];
    const float* W_hh     = (const float*)d_in[3];
    const float* b_ih     = (const float*)d_in[4];
    const float* b_hh     = (const float*)d_in[5];
    const float* Aw1      = (const float*)d_in[6];
    const float* Ab1      = (const float*)d_in[7];
    const float* Aw2      = (const float*)d_in[8];
    const float* Ab2      = (const float*)d_in[9];
    const float* Aw3      = (const float*)d_in[10];
    const float* Ab3      = (const float*)d_in[11];
    const float* Cw1      = (const float*)d_in[12];
    const float* Cb1      = (const float*)d_in[13];
    const float* Cw2      = (const float*)d_in[14];
    const float* Cb2      = (const float*)d_in[15];
    const float* Cw3      = (const float*)d_in[16];
    const float* Cb3      = (const float*)d_in[17];
    const float* log_std  = (const float*)d_in[18];
    const int*   starts   = (const int*)d_in[19];

    float* out      = (float*)d_out;
    float* out_main = out;
    float* out_std  = out + (size_t)MTOT * 13;
    float* out_h    = out + (size_t)MTOT * 13 + AA;

    float *xg, *lat, *t1, *t2a, *t2c, *wt, *wihr, *w1c, *w2a, *w2c, *b1c;
    cudaGetSymbolAddress((void**)&xg,   g_xg);
    cudaGetSymbolAddress((void**)&lat,  g_lat);
    cudaGetSymbolAddress((void**)&t1,   g_t1);
    cudaGetSymbolAddress((void**)&t2a,  g_t2a);
    cudaGetSymbolAddress((void**)&t2c,  g_t2c);
    cudaGetSymbolAddress((void**)&wt,   g_wt);
    cudaGetSymbolAddress((void**)&wihr, g_wihr);
    cudaGetSymbolAddress((void**)&w1c,  g_w1c);
    cudaGetSymbolAddress((void**)&w2a,  g_w2a);
    cudaGetSymbolAddress((void**)&w2c,  g_w2c);
    cudaGetSymbolAddress((void**)&b1c,  g_b1c);

    cudaFuncSetAttribute(gemm_mma<false, false>,
                         cudaFuncAttributeMaxDynamicSharedMemorySize, GEMM_SMEM);
    cudaFuncSetAttribute(gemm_mma<true, true>,
                         cudaFuncAttributeMaxDynamicSharedMemorySize, GEMM_SMEM);
    cudaFuncSetAttribute(gemm_mma<true, false>,
                         cudaFuncAttributeMaxDynamicSharedMemorySize, GEMM_SMEM);
    cudaFuncSetAttribute(gru_mma,
                         cudaFuncAttributeMaxDynamicSharedMemorySize, GRU_SMEM);

    dim3 blk(256);

    // Launch order fixed so ncu (-s 5 -c 1) profiles gru_mma (#6).
    // 1) W_hh transpose+round
    prep_whh<<<768, blk>>>(W_hh, wt);
    // 2) all other weights + bias concat
    prep_weights<<<448, blk>>>(
        (const float4*)W_ih, (const float4*)Aw1, (const float4*)Cw1,
        (const float4*)Aw2, (const float4*)Cw2,
        (const float4*)Ab1, (const float4*)Cb1,
        (float4*)wihr, (float4*)w1c, (float4*)w2a, (float4*)w2c, (float4*)b1c);
    // 3) features rounded
    round_copy4<<<((size_t)MTOT*256)/1024, blk>>>((const float4*)features, (float4*)t1);
    // 4) std (independent)
    std_kernel<<<1, 32>>>(log_std, out_std);
    // 5) xg = features @ W_ih^T + b_ih
    gemm_mma<false, false><<<dim3(G3/GBN, MTOT/GBM), blk, GEMM_SMEM>>>(
        t1, wihr, b_ih, xg, G3, FF, FF);
    // 6) GRU scan -> lat (tf32-rounded), h_last      <-- profiled launch
    gru_mma<<<BB/RB2, blk, GRU_SMEM>>>(xg, hidden, wt, b_hh, starts, lat, out_h);
    // 7) fused actor+critic layer1 (reuses g_xg as [M,512])
    gemm_mma<true, true><<<dim3(512/GBN, MTOT/GBM), blk, GEMM_SMEM>>>(
        lat, w1c, b1c, xg, 512, HH, HH);
    // 8,9) layer2 actor / critic
    gemm_mma<true, false><<<dim3(HH/GBN, MTOT/GBM), blk, GEMM_SMEM>>>(
        xg,       w2a, Ab2, t2a, HH, HH, 512);
    gemm_mma<true, false><<<dim3(HH/GBN, MTOT/GBM), blk, GEMM_SMEM>>>(
        xg + 256, w2c, Cb2, t2c, HH, HH, 512);
    // 10) heads
    head_kernel<<<MTOT/8, blk>>>(t2a, t2c, Aw3, Ab3, Cw3, Cb3, out_main);
}

// round 6
// speedup vs baseline: 1.0077x; 1.0077x over previous
#include <cuda_runtime.h>
#include <math.h>
#include <stdint.h>

// Problem dims
#define BB 4096
#define TT 64
#define FF 256
#define HH 256
#define AA 12
#define MTOT (BB*TT)            // 262144 rows
#define G3  768

// Scratch (device globals; no cudaMalloc allowed)
__device__ float g_xg [(size_t)MTOT * G3];     // xg, later reused as t12 [M,512]
__device__ float g_lat[(size_t)MTOT * HH];
__device__ float g_t1 [(size_t)MTOT * HH];     // rounded features
__device__ float g_t2a[(size_t)MTOT * HH];
__device__ float g_t2c[(size_t)MTOT * HH];
__device__ float g_wt  [256 * 768];            // W_hh^T rounded [k][gate]
__device__ float g_wihr[768 * 256];            // W_ih rounded
__device__ float g_w1c [512 * 256];            // [Aw1; Cw1] rounded
__device__ float g_w2a [256 * 256];
__device__ float g_w2c [256 * 256];
__device__ float g_b1c [512];                  // [Ab1 | Cb1]

__device__ __forceinline__ float round_tf32(float x) {
    uint32_t r;
    asm("cvt.rna.tf32.f32 %0, %1;" : "=r"(r) : "f"(x));
    return __uint_as_float(r);
}

__device__ __forceinline__ uint32_t smem_u32(const void* p) {
    uint32_t a;
    asm("{ .reg .u64 t; cvta.to.shared.u64 t, %1; cvt.u32.u64 %0, t; }"
        : "=r"(a) : "l"(p));
    return a;
}

__device__ __forceinline__ void cp16_cg(void* dst, const void* src) {
    asm volatile("cp.async.cg.shared.global [%0], [%1], 16;"
                 :: "r"(smem_u32(dst)), "l"(src) : "memory");
}
__device__ __forceinline__ void l2_prefetch(const void* p) {
    asm volatile("prefetch.global.L2 [%0];" :: "l"(p));
}
#define CP_COMMIT()  asm volatile("cp.async.commit_group;" ::: "memory")
#define CP_WAIT1()   asm volatile("cp.async.wait_group 1;" ::: "memory")
#define CP_WAITALL() asm volatile("cp.async.wait_all;" ::: "memory")

// ldmatrix fragment loaders (tf32 elements as b16 pairs; mapping == mma frags)
#define LDMX4(r0,r1,r2,r3,addr) \
    asm volatile("ldmatrix.sync.aligned.m8n8.x4.shared.b16 {%0,%1,%2,%3}, [%4];" \
                 : "=r"(r0),"=r"(r1),"=r"(r2),"=r"(r3) : "r"(addr))
#define LDMX2(r0,r1,addr) \
    asm volatile("ldmatrix.sync.aligned.m8n8.x2.shared.b16 {%0,%1}, [%2];" \
                 : "=r"(r0),"=r"(r1) : "r"(addr))

__device__ __forceinline__ void mma_tf32(
    float& c0, float& c1, float& c2, float& c3,
    uint32_t a0, uint32_t a1, uint32_t a2, uint32_t a3,
    uint32_t b0, uint32_t b1)
{
    asm volatile(
        "mma.sync.aligned.m16n8k8.row.col.f32.tf32.tf32.f32 "
        "{%0,%1,%2,%3}, {%4,%5,%6,%7}, {%8,%9}, {%0,%1,%2,%3};"
        : "+f"(c0), "+f"(c1), "+f"(c2), "+f"(c3)
        : "r"(a0), "r"(a1), "r"(a2), "r"(a3), "r"(b0), "r"(b1));
}

// ===========================================================================
// Prep: ALL weight prep in one kernel (keeps gru_mma at launch #4 for ncu).
// float4 segs: wihr 49152 | w1cA 16384 | w1cC 16384 | w2a 16384 | w2c 16384
// then scalar transpose of W_hh (196608 elems).
// ===========================================================================
#define PREP_F4 114688
__global__ void prep_all(
    const float4* __restrict__ Wih, const float4* __restrict__ Aw1,
    const float4* __restrict__ Cw1, const float4* __restrict__ Aw2,
    const float4* __restrict__ Cw2, const float4* __restrict__ Ab1,
    const float4* __restrict__ Cb1, const float*  __restrict__ W_hh,
    float4* __restrict__ wihr, float4* __restrict__ w1c,
    float4* __restrict__ w2a, float4* __restrict__ w2c,
    float4* __restrict__ b1c, float* __restrict__ Wt)
{
    int i = blockIdx.x * 256 + threadIdx.x;
    if (i < PREP_F4) {
        const float4* src;
        float4* dst;
        if (i < 49152)      { src = Wih + i;            dst = wihr + i; }
        else if (i < 65536) { src = Aw1 + (i - 49152);  dst = w1c + (i - 49152); }
        else if (i < 81920) { src = Cw1 + (i - 65536);  dst = w1c + 16384 + (i - 65536); }
        else if (i < 98304) { src = Aw2 + (i - 81920);  dst = w2a + (i - 81920); }
        else                { src = Cw2 + (i - 98304);  dst = w2c + (i - 98304); }
        float4 v = *src;
        v.x = round_tf32(v.x); v.y = round_tf32(v.y);
        v.z = round_tf32(v.z); v.w = round_tf32(v.w);
        *dst = v;
        if (i < 64)       b1c[i] = Ab1[i];
        else if (i < 128) b1c[i] = Cb1[i - 64];
    } else {
        int j = i - PREP_F4;               // 0..196607
        int g = j >> 8, k = j & 255;
        Wt[(size_t)k * 768 + g] = round_tf32(W_hh[(size_t)g * 256 + k]);
    }
}

__global__ void round_copy4(const float4* __restrict__ src, float4* __restrict__ dst)
{
    size_t i = (size_t)blockIdx.x * 256 + threadIdx.x;
    float4 v = src[i];
    v.x = round_tf32(v.x); v.y = round_tf32(v.y);
    v.z = round_tf32(v.z); v.w = round_tf32(v.w);
    dst[i] = v;
}

// ===========================================================================
// tf32 mma.sync GEMM, cp.async 2-stage, 2 CTAs/SM, ldmatrix fragments.
// C[M,N] = act(A[M,K] @ W[N,K]^T + bias[N]); A,W pre-rounded tf32.
// Tile 128x128x32, 256 threads (2x4 warps), warp tile 64x32.
// grid = (N/128, M/128)  -- N fastest for A reuse in L2.
// ===========================================================================
#define GBM 128
#define GBN 128
#define GBK 32
#define APITCH 36
#define STAGEF (GBM * APITCH)                 // 4608 floats (A or B)
#define GEMM_SMEM ((4 * STAGEF + GBN) * 4)    // 74240 bytes -> 2 CTAs/SM

template<bool DO_TANH, bool ROUND_OUT>
__global__ __launch_bounds__(256, 2) void gemm_mma(
    const float* __restrict__ A, const float* __restrict__ W,
    const float* __restrict__ bias, float* __restrict__ C,
    int N, int K, int lda)
{
    extern __shared__ float sm[];
    float* sBias = sm + 4 * STAGEF;

    const int tid  = threadIdx.x;
    const int lane = tid & 31;
    const int wid  = tid >> 5;
    const int wm   = wid >> 2;
    const int wn   = wid & 3;
    const int    bn = blockIdx.x * GBN;
    const size_t bm = (size_t)blockIdx.y * GBM;

    if (tid < GBN) sBias[tid] = bias[bn + tid];

    const int lrow = tid >> 1;
    const int lkq  = (tid & 1) * 16;
    const float* Ag = A + (bm + lrow) * lda + lkq;
    const float* Wg = W + ((size_t)(bn + lrow)) * K + lkq;

    // ldmatrix base offsets (floats)
    const uint32_t sbase = smem_u32(sm);
    const int a_lm = (wm * 64 + (lane & 15)) * APITCH + ((lane >> 4) << 2);
    const int b_lm = (wn * 32 + (lane & 7)) * APITCH + (((lane >> 3) & 1) << 2);

    float acc[4][4][4];
#pragma unroll
    for (int mt = 0; mt < 4; mt++)
#pragma unroll
        for (int nt = 0; nt < 4; nt++)
#pragma unroll
            for (int q = 0; q < 4; q++) acc[mt][nt][q] = 0.f;

    const int NK = K / GBK;

    auto stage_copy = [&](int kt) {
        float* st = sm + (kt & 1) * 2 * STAGEF;
        const float* ap = Ag + kt * GBK;
        const float* wp = Wg + kt * GBK;
        float* dA = st + lrow * APITCH + lkq;
        float* dB = st + STAGEF + lrow * APITCH + lkq;
#pragma unroll
        for (int u = 0; u < 4; u++) {
            cp16_cg(dA + 4 * u, ap + 4 * u);
            cp16_cg(dB + 4 * u, wp + 4 * u);
        }
    };

    stage_copy(0); CP_COMMIT();
    stage_copy(1); CP_COMMIT();

    for (int kt = 0; kt < NK; kt++) {
        if (kt < NK - 1) { CP_WAIT1(); } else { CP_WAITALL(); }
        __syncthreads();

        const uint32_t bufA = sbase + ((kt & 1) * 2 * STAGEF) * 4;
        const uint32_t bufB = bufA + STAGEF * 4;
#pragma unroll
        for (int k8 = 0; k8 < 4; k8++) {
            const int k0 = k8 * 8;
            uint32_t a[4][4];
#pragma unroll
            for (int mt = 0; mt < 4; mt++)
                LDMX4(a[mt][0], a[mt][1], a[mt][2], a[mt][3],
                      bufA + (a_lm + mt * 16 * APITCH + k0) * 4);
            uint32_t b[4][2];
#pragma unroll
            for (int nt = 0; nt < 4; nt++)
                LDMX2(b[nt][0], b[nt][1],
                      bufB + (b_lm + nt * 8 * APITCH + k0) * 4);
#pragma unroll
            for (int mt = 0; mt < 4; mt++)
#pragma unroll
                for (int nt = 0; nt < 4; nt++)
                    mma_tf32(acc[mt][nt][0], acc[mt][nt][1],
                             acc[mt][nt][2], acc[mt][nt][3],
                             a[mt][0], a[mt][1], a[mt][2], a[mt][3],
                             b[nt][0], b[nt][1]);
        }
        __syncthreads();
        if (kt + 2 < NK) { stage_copy(kt + 2); CP_COMMIT(); }
    }

    // epilogue
#pragma unroll
    for (int mt = 0; mt < 4; mt++) {
        const size_t row = bm + wm * 64 + mt * 16 + (lane >> 2);
        float* c0p = C + row * N + bn + wn * 32;
        float* c1p = c0p + (size_t)8 * N;
#pragma unroll
        for (int nt = 0; nt < 4; nt++) {
            const int cc = nt * 8 + (lane & 3) * 2;
            const float bx = sBias[wn * 32 + cc];
            const float by = sBias[wn * 32 + cc + 1];
            float v0 = acc[mt][nt][0] + bx, v1 = acc[mt][nt][1] + by;
            float v2 = acc[mt][nt][2] + bx, v3 = acc[mt][nt][3] + by;
            if (DO_TANH) {
                v0 = tanhf(v0); v1 = tanhf(v1);
                v2 = tanhf(v2); v3 = tanhf(v3);
            }
            if (ROUND_OUT) {
                v0 = round_tf32(v0); v1 = round_tf32(v1);
                v2 = round_tf32(v2); v3 = round_tf32(v3);
            }
            *(float2*)(c0p + cc) = make_float2(v0, v1);
            *(float2*)(c1p + cc) = make_float2(v2, v3);
        }
    }
}

// ===========================================================================
// GRU scan: mma.sync tf32, continuous 3-stage cp.async W pipeline,
// 1 barrier per k-tile, ldmatrix A-fragments, L2 prefetch of xg[t].
// RB=32 rows/block, 128 blocks, 256 threads.
// ===========================================================================
#define RB2 32
#define HF_PITCH 257
#define HT_PITCH 260
#define WS_PITCH 776
#define WS_STAGE (16 * WS_PITCH)
// smem: ws[3][16][776] | hf[32][257] | ht[32][260] | sst[32][64] | sbh[768]
#define GRU_SMEM ((3*WS_STAGE + 32*HF_PITCH + 32*HT_PITCH + 768) * 4 + 32*64*4)

__global__ __launch_bounds__(256, 1) void gru_mma(
    const float* __restrict__ xg, const float* __restrict__ h0,
    const float* __restrict__ Wt, const float* __restrict__ b_hh,
    const int* __restrict__ starts,
    float* __restrict__ lat, float* __restrict__ h_out)
{
    extern __shared__ float sm[];
    float* ws  = sm;                          // [3][16][776]
    float* hf  = ws + 3 * WS_STAGE;           // [32][257]
    float* ht  = hf + 32 * HF_PITCH;          // [32][260]
    int*   sst = (int*)(ht + 32 * HT_PITCH);  // [32][64]
    float* sbh = (float*)(sst + 32 * 64);     // [768]

    const int tid  = threadIdx.x;
    const int lane = tid & 31;
    const int w    = tid >> 5;
    const int b0   = blockIdx.x * RB2;

    for (int i = tid; i < 32 * 64; i += 256)
        sst[i] = starts[(size_t)(b0 + (i >> 6)) * TT + (i & 63)];
    for (int i = tid; i < 768; i += 256) sbh[i] = b_hh[i];
    for (int i = tid; i < 32 * 256; i += 256) {
        int r = i >> 8, c = i & 255;
        float v = h0[(size_t)(b0 + r) * 256 + c];
        if (starts[(size_t)(b0 + r) * TT]) v = 0.f;
        hf[r * HF_PITCH + c] = v;
        ht[r * HT_PITCH + c] = round_tf32(v);
    }

    const int krow = tid >> 4;        // 0..15
    const int c4   = (tid & 15) * 4;

    // ldmatrix A base offset into ht (floats)
    const uint32_t ht_lm = smem_u32(ht)
        + (((lane & 15)) * HT_PITCH + ((lane >> 4) << 2)) * 4;

    auto stageW = [&](int tile, int buf) {
        const float* src = Wt + (size_t)(tile * 16 + krow) * 768 + c4;
        float* dst = ws + buf * WS_STAGE + krow * WS_PITCH + c4;
#pragma unroll
        for (int u = 0; u < 12; u++)
            cp16_cg(dst + u * 64, src + u * 64);
    };

    stageW(0, 0); CP_COMMIT();
    stageW(1, 1); CP_COMMIT();

    const int KS_TOTAL = TT * 16;     // 1024
    int ks = 0;

    for (int t = 0; t < TT; t++) {
        float acc[2][12][4];
#pragma unroll
        for (int mt = 0; mt < 2; mt++)
#pragma unroll
            for (int j = 0; j < 12; j++)
#pragma unroll
                for (int q = 0; q < 4; q++) acc[mt][j][q] = 0.f;

        for (int kt = 0; kt < 16; kt++) {
            if (ks < KS_TOTAL - 1) { CP_WAIT1(); } else { CP_WAITALL(); }
            __syncthreads();   // stage ks ready; kt==0 also orders ht writes

            if (ks + 2 < KS_TOTAL) {
                stageW((ks + 2) & 15, (ks + 2) % 3);
                CP_COMMIT();
            }

            // L2 prefetch of xg[t] slice
            if (tid < 48) {
                int li = kt * 48 + tid;
                int r = li / 24, cl = li % 24;
                l2_prefetch(xg + ((size_t)(b0 + r) * TT + t) * G3 + cl * 32);
            }

            const int buf = ks % 3;
#pragma unroll
            for (int s = 0; s < 2; s++) {
                const int kg = kt * 16 + s * 8;
                uint32_t a[2][4];
#pragma unroll
                for (int mt = 0; mt < 2; mt++)
                    LDMX4(a[mt][0], a[mt][1], a[mt][2], a[mt][3],
                          ht_lm + (mt * 16 * HT_PITCH + kg) * 4);
                const float* wb = ws + buf * WS_STAGE
                                + (s * 8 + (lane & 3)) * WS_PITCH;
#pragma unroll
                for (int g = 0; g < 3; g++)
#pragma unroll
                    for (int nt = 0; nt < 4; nt++) {
                        const int col = g * 256 + w * 32 + nt * 8 + (lane >> 2);
                        uint32_t bb0 = __float_as_uint(wb[col]);
                        uint32_t bb1 = __float_as_uint(wb[4 * WS_PITCH + col]);
                        const int j = g * 4 + nt;
                        mma_tf32(acc[0][j][0], acc[0][j][1], acc[0][j][2], acc[0][j][3],
                                 a[0][0], a[0][1], a[0][2], a[0][3], bb0, bb1);
                        mma_tf32(acc[1][j][0], acc[1][j][1], acc[1][j][2], acc[1][j][3],
                                 a[1][0], a[1][1], a[1][2], a[1][3], bb0, bb1);
                    }
            }
            ks++;
        }
        __syncthreads();   // all mma reads of ht done before pointwise writes

        // pointwise GRU update
#pragma unroll
        for (int mt = 0; mt < 2; mt++)
#pragma unroll
        for (int rh = 0; rh < 2; rh++) {
            const int row  = mt * 16 + rh * 8 + (lane >> 2);
            const int grow = b0 + row;
            const size_t gbt = (size_t)grow * TT + t;
            const float* xb = xg + gbt * 768;
            float* lb = lat + gbt * 256;
            float msk = 1.f;
            if (t < TT - 1) msk = sst[row * 64 + t + 1] ? 0.f : 1.f;
#pragma unroll
            for (int nt = 0; nt < 4; nt++) {
                const int c = w * 32 + nt * 8 + (lane & 3) * 2;
                float2 xr = *(const float2*)(xb + c);
                float2 xz = *(const float2*)(xb + 256 + c);
                float2 xn = *(const float2*)(xb + 512 + c);
                const int q = rh * 2;
                float hr0 = acc[mt][nt][q]     + sbh[c];
                float hr1 = acc[mt][nt][q + 1] + sbh[c + 1];
                float hz0 = acc[mt][4 + nt][q]     + sbh[256 + c];
                float hz1 = acc[mt][4 + nt][q + 1] + sbh[256 + c + 1];
                float hn0 = acc[mt][8 + nt][q]     + sbh[512 + c];
                float hn1 = acc[mt][8 + nt][q + 1] + sbh[512 + c + 1];
                float r0 = 1.f / (1.f + __expf(-(xr.x + hr0)));
                float r1 = 1.f / (1.f + __expf(-(xr.y + hr1)));
                float z0 = 1.f / (1.f + __expf(-(xz.x + hz0)));
                float z1 = 1.f / (1.f + __expf(-(xz.y + hz1)));
                float n0 = tanhf(xn.x + r0 * hn0);
                float n1 = tanhf(xn.y + r1 * hn1);
                float ho0 = hf[row * HF_PITCH + c];
                float ho1 = hf[row * HF_PITCH + c + 1];
                float v0 = (1.f - z0) * n0 + z0 * ho0;
                float v1 = (1.f - z1) * n1 + z1 * ho1;
                *(float2*)(lb + c) = make_float2(round_tf32(v0), round_tf32(v1));
                if (t == TT - 1) {
                    *(float2*)(h_out + (size_t)grow * 256 + c) = make_float2(v0, v1);
                } else {
                    float m0 = v0 * msk, m1 = v1 * msk;
                    hf[row * HF_PITCH + c]     = m0;
                    hf[row * HF_PITCH + c + 1] = m1;
                    ht[row * HT_PITCH + c]     = round_tf32(m0);
                    ht[row * HT_PITCH + c + 1] = round_tf32(m1);
                }
            }
        }
        // next t's kt=0 barrier orders these writes vs mma reads
    }
}

// ---------------------------------------------------------------------------
// Heads
// ---------------------------------------------------------------------------
__global__ __launch_bounds__(256) void head_kernel(
    const float* __restrict__ t2a, const float* __restrict__ t2c,
    const float* __restrict__ Aw3, const float* __restrict__ Ab3,
    const float* __restrict__ Cw3, const float* __restrict__ Cb3,
    float* __restrict__ out)
{
    __shared__ float wa[12][256];
    __shared__ float wc[256];
    __shared__ float ba[12];
    __shared__ float bc;

    const int tid = threadIdx.x;
    for (int i = tid; i < 12 * 256; i += 256) wa[i >> 8][i & 255] = Aw3[i];
    if (tid < 256) wc[tid] = Cw3[tid];
    if (tid < 12)  ba[tid] = Ab3[tid];
    if (tid == 0)  bc = Cb3[0];
    __syncthreads();

    const int warp = tid >> 5;
    const int lane = tid & 31;
    const size_t row = (size_t)blockIdx.x * 8 + warp;

    const float* ra = t2a + row * 256;
    const float* rc = t2c + row * 256;
    float va[8], vc[8];
#pragma unroll
    for (int u = 0; u < 8; u++) {
        va[u] = ra[lane + 32 * u];
        vc[u] = rc[lane + 32 * u];
    }

    float s[13];
#pragma unroll
    for (int a = 0; a < 12; a++) {
        float acc = 0.f;
#pragma unroll
        for (int u = 0; u < 8; u++) acc = fmaf(va[u], wa[a][lane + 32 * u], acc);
        s[a] = acc;
    }
    {
        float acc = 0.f;
#pragma unroll
        for (int u = 0; u < 8; u++) acc = fmaf(vc[u], wc[lane + 32 * u], acc);
        s[12] = acc;
    }
#pragma unroll
    for (int a = 0; a < 13; a++)
#pragma unroll
        for (int o = 16; o > 0; o >>= 1)
            s[a] += __shfl_xor_sync(0xffffffffu, s[a], o);
    if (lane == 0) {
        float* o = out + row * 13;
#pragma unroll
        for (int a = 0; a < 12; a++) o[a] = s[a] + ba[a];
        o[12] = s[12] + bc;
    }
}

__global__ void std_kernel(const float* __restrict__ log_std, float* __restrict__ out)
{
    int a = threadIdx.x;
    if (a < AA) {
        float v = log_std[a];
        v = fminf(fmaxf(v, -2.0f), -0.5f);
        out[a] = __expf(v);
    }
}

// ---------------------------------------------------------------------------
extern "C" void kernel_launch(void* const* d_in, const int* in_sizes, int n_in,
                              void* d_out, int out_size)
{
    const float* features = (const float*)d_in[0];
    const float* hidden   = (const float*)d_in[1];
    const float* W_ih     = (const float*)d_in[2];
    const float* W_hh     = (const float*)d_in[3];
    const float* b_ih     = (const float*)d_in[4];
    const float* b_hh     = (const float*)d_in[5];
    const float* Aw1      = (const float*)d_in[6];
    const float* Ab1      = (const float*)d_in[7];
    const float* Aw2      = (const float*)d_in[8];
    const float* Ab2      = (const float*)d_in[9];
    const float* Aw3      = (const float*)d_in[10];
    const float* Ab3      = (const float*)d_in[11];
    const float* Cw1      = (const float*)d_in[12];
    const float* Cb1      = (const float*)d_in[13];
    const float* Cw2      = (const float*)d_in[14];
    const float* Cb2      = (const float*)d_in[15];
    const float* Cw3      = (const float*)d_in[16];
    const float* Cb3      = (const float*)d_in[17];
    const float* log_std  = (const float*)d_in[18];
    const int*   starts   = (const int*)d_in[19];

    float* out      = (float*)d_out;
    float* out_main = out;
    float* out_std  = out + (size_t)MTOT * 13;
    float* out_h    = out + (size_t)MTOT * 13 + AA;

    float *xg, *lat, *t1, *t2a, *t2c, *wt, *wihr, *w1c, *w2a, *w2c, *b1c;
    cudaGetSymbolAddress((void**)&xg,   g_xg);
    cudaGetSymbolAddress((void**)&lat,  g_lat);
    cudaGetSymbolAddress((void**)&t1,   g_t1);
    cudaGetSymbolAddress((void**)&t2a,  g_t2a);
    cudaGetSymbolAddress((void**)&t2c,  g_t2c);
    cudaGetSymbolAddress((void**)&wt,   g_wt);
    cudaGetSymbolAddress((void**)&wihr, g_wihr);
    cudaGetSymbolAddress((void**)&w1c,  g_w1c);
    cudaGetSymbolAddress((void**)&w2a,  g_w2a);
    cudaGetSymbolAddress((void**)&w2c,  g_w2c);
    cudaGetSymbolAddress((void**)&b1c,  g_b1c);

    cudaFuncSetAttribute(gemm_mma<false, false>,
                         cudaFuncAttributeMaxDynamicSharedMemorySize, GEMM_SMEM);
    cudaFuncSetAttribute(gemm_mma<true, true>,
                         cudaFuncAttributeMaxDynamicSharedMemorySize, GEMM_SMEM);
    cudaFuncSetAttribute(gemm_mma<true, false>,
                         cudaFuncAttributeMaxDynamicSharedMemorySize, GEMM_SMEM);
    cudaFuncSetAttribute(gru_mma,
                         cudaFuncAttributeMaxDynamicSharedMemorySize, GRU_SMEM);

    dim3 blk(256);

    // Launch order: gru_mma is launch #4 (ncu profiles the 4th launch).
    // 1) all weight prep (round + W_hh transpose + bias concat)
    prep_all<<<1216, blk>>>(
        (const float4*)W_ih, (const float4*)Aw1, (const float4*)Cw1,
        (const float4*)Aw2, (const float4*)Cw2,
        (const float4*)Ab1, (const float4*)Cb1, W_hh,
        (float4*)wihr, (float4*)w1c, (float4*)w2a, (float4*)w2c,
        (float4*)b1c, wt);
    // 2) features rounded
    round_copy4<<<((size_t)MTOT*256)/1024, blk>>>((const float4*)features, (float4*)t1);
    // 3) xg = features @ W_ih^T + b_ih
    gemm_mma<false, false><<<dim3(G3/GBN, MTOT/GBM), blk, GEMM_SMEM>>>(
        t1, wihr, b_ih, xg, G3, FF, FF);
    // 4) GRU scan -> lat (tf32-rounded), h_last      <-- profiled launch
    gru_mma<<<BB/RB2, blk, GRU_SMEM>>>(xg, hidden, wt, b_hh, starts, lat, out_h);
    // 5) fused actor+critic layer1 (reuses g_xg as [M,512])
    gemm_mma<true, true><<<dim3(512/GBN, MTOT/GBM), blk, GEMM_SMEM>>>(
        lat, w1c, b1c, xg, 512, HH, HH);
    // 6,7) layer2 actor / critic
    gemm_mma<true, false><<<dim3(HH/GBN, MTOT/GBM), blk, GEMM_SMEM>>>(
        xg,       w2a, Ab2, t2a, HH, HH, 512);
    gemm_mma<true, false><<<dim3(HH/GBN, MTOT/GBM), blk, GEMM_SMEM>>>(
        xg + 256, w2c, Cb2, t2c, HH, HH, 512);
    // 8) heads
    head_kernel<<<MTOT/8, blk>>>(t2a, t2c, Aw3, Ab3, Cw3, Cb3, out_main);
    // 9) std
    std_kernel<<<1, 32>>>(log_std, out_std);
}

// round 7
// speedup vs baseline: 1.0501x; 1.0421x over previous
#include <cuda_runtime.h>
#include <math.h>
#include <stdint.h>

// Problem dims
#define BB 4096
#define TT 64
#define FF 256
#define HH 256
#define AA 12
#define MTOT (BB*TT)            // 262144 rows
#define G3  768

// Scratch (device globals; no cudaMalloc allowed)
__device__ float g_xg [(size_t)MTOT * G3];     // xg, later reused as t12 [M,512]
__device__ float g_lat[(size_t)MTOT * HH];
__device__ float g_t1 [(size_t)MTOT * HH];     // rounded features
__device__ float g_t2a[(size_t)MTOT * HH];
__device__ float g_t2c[(size_t)MTOT * HH];
__device__ float g_wt  [256 * 768];            // W_hh^T rounded [k][gate]
__device__ float g_wihr[768 * 256];            // W_ih rounded
__device__ float g_w1c [512 * 256];            // [Aw1; Cw1] rounded
__device__ float g_w2a [256 * 256];
__device__ float g_w2c [256 * 256];
__device__ float g_b1c [512];                  // [Ab1 | Cb1]

__device__ __forceinline__ float round_tf32(float x) {
    uint32_t r;
    asm("cvt.rna.tf32.f32 %0, %1;" : "=r"(r) : "f"(x));
    return __uint_as_float(r);
}

__device__ __forceinline__ uint32_t smem_u32(const void* p) {
    uint32_t a;
    asm("{ .reg .u64 t; cvta.to.shared.u64 t, %1; cvt.u32.u64 %0, t; }"
        : "=r"(a) : "l"(p));
    return a;
}

__device__ __forceinline__ void cp16_cg(void* dst, const void* src) {
    asm volatile("cp.async.cg.shared.global [%0], [%1], 16;"
                 :: "r"(smem_u32(dst)), "l"(src) : "memory");
}
__device__ __forceinline__ void l2_prefetch(const void* p) {
    asm volatile("prefetch.global.L2 [%0];" :: "l"(p));
}
#define CP_COMMIT()  asm volatile("cp.async.commit_group;" ::: "memory")
#define CP_WAIT1()   asm volatile("cp.async.wait_group 1;" ::: "memory")
#define CP_WAITALL() asm volatile("cp.async.wait_all;" ::: "memory")

// ldmatrix fragment loaders (tf32 elements as b16 pairs; mapping == mma frags)
#define LDMX4(r0,r1,r2,r3,addr) \
    asm volatile("ldmatrix.sync.aligned.m8n8.x4.shared.b16 {%0,%1,%2,%3}, [%4];" \
                 : "=r"(r0),"=r"(r1),"=r"(r2),"=r"(r3) : "r"(addr))
#define LDMX2(r0,r1,addr) \
    asm volatile("ldmatrix.sync.aligned.m8n8.x2.shared.b16 {%0,%1}, [%2];" \
                 : "=r"(r0),"=r"(r1) : "r"(addr))

__device__ __forceinline__ void mma_tf32(
    float& c0, float& c1, float& c2, float& c3,
    uint32_t a0, uint32_t a1, uint32_t a2, uint32_t a3,
    uint32_t b0, uint32_t b1)
{
    asm volatile(
        "mma.sync.aligned.m16n8k8.row.col.f32.tf32.tf32.f32 "
        "{%0,%1,%2,%3}, {%4,%5,%6,%7}, {%8,%9}, {%0,%1,%2,%3};"
        : "+f"(c0), "+f"(c1), "+f"(c2), "+f"(c3)
        : "r"(a0), "r"(a1), "r"(a2), "r"(a3), "r"(b0), "r"(b1));
}

// ===========================================================================
// Prep: ALL weight prep in one kernel (keeps gru_mma at launch #4 for ncu).
// ===========================================================================
#define PREP_F4 114688
__global__ void prep_all(
    const float4* __restrict__ Wih, const float4* __restrict__ Aw1,
    const float4* __restrict__ Cw1, const float4* __restrict__ Aw2,
    const float4* __restrict__ Cw2, const float4* __restrict__ Ab1,
    const float4* __restrict__ Cb1, const float*  __restrict__ W_hh,
    float4* __restrict__ wihr, float4* __restrict__ w1c,
    float4* __restrict__ w2a, float4* __restrict__ w2c,
    float4* __restrict__ b1c, float* __restrict__ Wt)
{
    int i = blockIdx.x * 256 + threadIdx.x;
    if (i < PREP_F4) {
        const float4* src;
        float4* dst;
        if (i < 49152)      { src = Wih + i;            dst = wihr + i; }
        else if (i < 65536) { src = Aw1 + (i - 49152);  dst = w1c + (i - 49152); }
        else if (i < 81920) { src = Cw1 + (i - 65536);  dst = w1c + 16384 + (i - 65536); }
        else if (i < 98304) { src = Aw2 + (i - 81920);  dst = w2a + (i - 81920); }
        else                { src = Cw2 + (i - 98304);  dst = w2c + (i - 98304); }
        float4 v = *src;
        v.x = round_tf32(v.x); v.y = round_tf32(v.y);
        v.z = round_tf32(v.z); v.w = round_tf32(v.w);
        *dst = v;
        if (i < 64)       b1c[i] = Ab1[i];
        else if (i < 128) b1c[i] = Cb1[i - 64];
    } else {
        int j = i - PREP_F4;               // 0..196607
        int g = j >> 8, k = j & 255;
        Wt[(size_t)k * 768 + g] = round_tf32(W_hh[(size_t)g * 256 + k]);
    }
}

__global__ void round_copy4(const float4* __restrict__ src, float4* __restrict__ dst)
{
    size_t i = (size_t)blockIdx.x * 256 + threadIdx.x;
    float4 v = src[i];
    v.x = round_tf32(v.x); v.y = round_tf32(v.y);
    v.z = round_tf32(v.z); v.w = round_tf32(v.w);
    dst[i] = v;
}

// ===========================================================================
// tf32 mma.sync GEMM, cp.async 2-stage, 2 CTAs/SM, ldmatrix fragments.
// (unchanged from R6)
// ===========================================================================
#define GBM 128
#define GBN 128
#define GBK 32
#define APITCH 36
#define STAGEF (GBM * APITCH)                 // 4608 floats (A or B)
#define GEMM_SMEM ((4 * STAGEF + GBN) * 4)    // 74240 bytes -> 2 CTAs/SM

template<bool DO_TANH, bool ROUND_OUT>
__global__ __launch_bounds__(256, 2) void gemm_mma(
    const float* __restrict__ A, const float* __restrict__ W,
    const float* __restrict__ bias, float* __restrict__ C,
    int N, int K, int lda)
{
    extern __shared__ float sm[];
    float* sBias = sm + 4 * STAGEF;

    const int tid  = threadIdx.x;
    const int lane = tid & 31;
    const int wid  = tid >> 5;
    const int wm   = wid >> 2;
    const int wn   = wid & 3;
    const int    bn = blockIdx.x * GBN;
    const size_t bm = (size_t)blockIdx.y * GBM;

    if (tid < GBN) sBias[tid] = bias[bn + tid];

    const int lrow = tid >> 1;
    const int lkq  = (tid & 1) * 16;
    const float* Ag = A + (bm + lrow) * lda + lkq;
    const float* Wg = W + ((size_t)(bn + lrow)) * K + lkq;

    const uint32_t sbase = smem_u32(sm);
    const int a_lm = (wm * 64 + (lane & 15)) * APITCH + ((lane >> 4) << 2);
    const int b_lm = (wn * 32 + (lane & 7)) * APITCH + (((lane >> 3) & 1) << 2);

    float acc[4][4][4];
#pragma unroll
    for (int mt = 0; mt < 4; mt++)
#pragma unroll
        for (int nt = 0; nt < 4; nt++)
#pragma unroll
            for (int q = 0; q < 4; q++) acc[mt][nt][q] = 0.f;

    const int NK = K / GBK;

    auto stage_copy = [&](int kt) {
        float* st = sm + (kt & 1) * 2 * STAGEF;
        const float* ap = Ag + kt * GBK;
        const float* wp = Wg + kt * GBK;
        float* dA = st + lrow * APITCH + lkq;
        float* dB = st + STAGEF + lrow * APITCH + lkq;
#pragma unroll
        for (int u = 0; u < 4; u++) {
            cp16_cg(dA + 4 * u, ap + 4 * u);
            cp16_cg(dB + 4 * u, wp + 4 * u);
        }
    };

    stage_copy(0); CP_COMMIT();
    stage_copy(1); CP_COMMIT();

    for (int kt = 0; kt < NK; kt++) {
        if (kt < NK - 1) { CP_WAIT1(); } else { CP_WAITALL(); }
        __syncthreads();

        const uint32_t bufA = sbase + ((kt & 1) * 2 * STAGEF) * 4;
        const uint32_t bufB = bufA + STAGEF * 4;
#pragma unroll
        for (int k8 = 0; k8 < 4; k8++) {
            const int k0 = k8 * 8;
            uint32_t a[4][4];
#pragma unroll
            for (int mt = 0; mt < 4; mt++)
                LDMX4(a[mt][0], a[mt][1], a[mt][2], a[mt][3],
                      bufA + (a_lm + mt * 16 * APITCH + k0) * 4);
            uint32_t b[4][2];
#pragma unroll
            for (int nt = 0; nt < 4; nt++)
                LDMX2(b[nt][0], b[nt][1],
                      bufB + (b_lm + nt * 8 * APITCH + k0) * 4);
#pragma unroll
            for (int mt = 0; mt < 4; mt++)
#pragma unroll
                for (int nt = 0; nt < 4; nt++)
                    mma_tf32(acc[mt][nt][0], acc[mt][nt][1],
                             acc[mt][nt][2], acc[mt][nt][3],
                             a[mt][0], a[mt][1], a[mt][2], a[mt][3],
                             b[nt][0], b[nt][1]);
        }
        __syncthreads();
        if (kt + 2 < NK) { stage_copy(kt + 2); CP_COMMIT(); }
    }

#pragma unroll
    for (int mt = 0; mt < 4; mt++) {
        const size_t row = bm + wm * 64 + mt * 16 + (lane >> 2);
        float* c0p = C + row * N + bn + wn * 32;
        float* c1p = c0p + (size_t)8 * N;
#pragma unroll
        for (int nt = 0; nt < 4; nt++) {
            const int cc = nt * 8 + (lane & 3) * 2;
            const float bx = sBias[wn * 32 + cc];
            const float by = sBias[wn * 32 + cc + 1];
            float v0 = acc[mt][nt][0] + bx, v1 = acc[mt][nt][1] + by;
            float v2 = acc[mt][nt][2] + bx, v3 = acc[mt][nt][3] + by;
            if (DO_TANH) {
                v0 = tanhf(v0); v1 = tanhf(v1);
                v2 = tanhf(v2); v3 = tanhf(v3);
            }
            if (ROUND_OUT) {
                v0 = round_tf32(v0); v1 = round_tf32(v1);
                v2 = round_tf32(v2); v3 = round_tf32(v3);
            }
            *(float2*)(c0p + cc) = make_float2(v0, v1);
            *(float2*)(c1p + cc) = make_float2(v2, v3);
        }
    }
}

// ===========================================================================
// GRU scan: 512 threads (16 warps), warp = 16 rows x 32 cols x 3 gates.
// fp32 h in REGISTERS (owner thread), tf32 copy in smem for ldmatrix.
// Continuous 3-stage cp.async W pipeline, 1 barrier/kt, xg L2 prefetch.
// RB=32 rows/block, 128 blocks.
// ===========================================================================
#define RB2 32
#define HT_PITCH 260
#define WS_PITCH 776
#define WS_STAGE (16 * WS_PITCH)
// smem: ws[3][16][776] | ht[32][260] | sst[32][64] | sbh[768]
#define GRU_SMEM ((3*WS_STAGE + 32*HT_PITCH + 768) * 4 + 32*64*4)

__global__ __launch_bounds__(512, 1) void gru_mma(
    const float* __restrict__ xg, const float* __restrict__ h0,
    const float* __restrict__ Wt, const float* __restrict__ b_hh,
    const int* __restrict__ starts,
    float* __restrict__ lat, float* __restrict__ h_out)
{
    extern __shared__ float sm[];
    float* ws  = sm;                          // [3][16][776]
    float* ht  = ws + 3 * WS_STAGE;           // [32][260]
    int*   sst = (int*)(ht + 32 * HT_PITCH);  // [32][64]
    float* sbh = (float*)(sst + 32 * 64);     // [768]

    const int tid  = threadIdx.x;
    const int lane = tid & 31;
    const int w    = tid >> 5;      // 0..15
    const int wm   = w >> 3;        // 0..1: row half
    const int wn   = w & 7;         // 0..7: 32-col group
    const int b0   = blockIdx.x * RB2;

    for (int i = tid; i < 32 * 64; i += 512)
        sst[i] = starts[(size_t)(b0 + (i >> 6)) * TT + (i & 63)];
    for (int i = tid; i < 768; i += 512) sbh[i] = b_hh[i];

    // fp32 h in registers: thread owns rows wm*16+rh*8+(lane>>2), cols
    // wn*32+nt*8+(lane&3)*2 (+1). Init from h0 with t=0 start mask; also
    // populate tf32 smem copy.
    float2 hreg[2][4];
#pragma unroll
    for (int rh = 0; rh < 2; rh++) {
        const int row = wm * 16 + rh * 8 + (lane >> 2);
        const float m0 = starts[(size_t)(b0 + row) * TT] ? 0.f : 1.f;
#pragma unroll
        for (int nt = 0; nt < 4; nt++) {
            const int c = wn * 32 + nt * 8 + (lane & 3) * 2;
            float2 v = *(const float2*)(h0 + (size_t)(b0 + row) * 256 + c);
            v.x *= m0; v.y *= m0;
            hreg[rh][nt] = v;
            ht[row * HT_PITCH + c]     = round_tf32(v.x);
            ht[row * HT_PITCH + c + 1] = round_tf32(v.y);
        }
    }

    // W staging: 32 threads per k-row, 16 rows
    const int krow = tid >> 5;          // 0..15
    const int c4   = (tid & 31) * 4;    // 0..124 step 4

    auto stageW = [&](int tile, int buf) {
        const float* src = Wt + (size_t)(tile * 16 + krow) * 768 + c4;
        float* dst = ws + buf * WS_STAGE + krow * WS_PITCH + c4;
#pragma unroll
        for (int u = 0; u < 6; u++)
            cp16_cg(dst + u * 128, src + u * 128);
    };

    stageW(0, 0); CP_COMMIT();
    stageW(1, 1); CP_COMMIT();

    // ldmatrix A base (16x8 tf32 tile at rows wm*16..+16)
    const uint32_t ht_lm = smem_u32(ht)
        + ((wm * 16 + (lane & 15)) * HT_PITCH + ((lane >> 4) << 2)) * 4;

    const int KS_TOTAL = TT * 16;     // 1024
    int ks = 0;

    for (int t = 0; t < TT; t++) {
        float acc[12][4];
#pragma unroll
        for (int j = 0; j < 12; j++)
#pragma unroll
            for (int q = 0; q < 4; q++) acc[j][q] = 0.f;

        for (int kt = 0; kt < 16; kt++) {
            if (ks < KS_TOTAL - 1) { CP_WAIT1(); } else { CP_WAITALL(); }
            __syncthreads();   // stage ks ready; kt==0 also orders ht writes

            if (ks + 2 < KS_TOTAL) {
                stageW((ks + 2) & 15, (ks + 2) % 3);
                CP_COMMIT();
            }

            if (tid < 48) {
                int li = kt * 48 + tid;
                int r = li / 24, cl = li % 24;
                l2_prefetch(xg + ((size_t)(b0 + r) * TT + t) * G3 + cl * 32);
            }

            const int buf = ks % 3;
#pragma unroll
            for (int s = 0; s < 2; s++) {
                const int kg = kt * 16 + s * 8;
                uint32_t a0, a1, a2, a3;
                LDMX4(a0, a1, a2, a3, ht_lm + kg * 4);
                const float* wb = ws + buf * WS_STAGE
                                + (s * 8 + (lane & 3)) * WS_PITCH;
#pragma unroll
                for (int g = 0; g < 3; g++)
#pragma unroll
                    for (int nt = 0; nt < 4; nt++) {
                        const int col = g * 256 + wn * 32 + nt * 8 + (lane >> 2);
                        uint32_t bb0 = __float_as_uint(wb[col]);
                        uint32_t bb1 = __float_as_uint(wb[4 * WS_PITCH + col]);
                        const int j = g * 4 + nt;
                        mma_tf32(acc[j][0], acc[j][1], acc[j][2], acc[j][3],
                                 a0, a1, a2, a3, bb0, bb1);
                    }
            }
            ks++;
        }
        __syncthreads();   // mma reads of ht done before pointwise writes

        // pointwise GRU update (h fp32 in registers)
#pragma unroll
        for (int rh = 0; rh < 2; rh++) {
            const int row  = wm * 16 + rh * 8 + (lane >> 2);
            const int grow = b0 + row;
            const size_t gbt = (size_t)grow * TT + t;
            const float* xb = xg + gbt * 768;
            float* lb = lat + gbt * 256;
            float msk = 1.f;
            if (t < TT - 1) msk = sst[row * 64 + t + 1] ? 0.f : 1.f;
            const int q = rh * 2;
#pragma unroll
            for (int nt = 0; nt < 4; nt++) {
                const int c = wn * 32 + nt * 8 + (lane & 3) * 2;
                float2 xr = *(const float2*)(xb + c);
                float2 xz = *(const float2*)(xb + 256 + c);
                float2 xn = *(const float2*)(xb + 512 + c);
                float hr0 = acc[nt][q]         + sbh[c];
                float hr1 = acc[nt][q + 1]     + sbh[c + 1];
                float hz0 = acc[4 + nt][q]     + sbh[256 + c];
                float hz1 = acc[4 + nt][q + 1] + sbh[256 + c + 1];
                float hn0 = acc[8 + nt][q]     + sbh[512 + c];
                float hn1 = acc[8 + nt][q + 1] + sbh[512 + c + 1];
                float r0 = 1.f / (1.f + __expf(-(xr.x + hr0)));
                float r1 = 1.f / (1.f + __expf(-(xr.y + hr1)));
                float z0 = 1.f / (1.f + __expf(-(xz.x + hz0)));
                float z1 = 1.f / (1.f + __expf(-(xz.y + hz1)));
                float n0 = tanhf(xn.x + r0 * hn0);
                float n1 = tanhf(xn.y + r1 * hn1);
                float v0 = (1.f - z0) * n0 + z0 * hreg[rh][nt].x;
                float v1 = (1.f - z1) * n1 + z1 * hreg[rh][nt].y;
                *(float2*)(lb + c) = make_float2(round_tf32(v0), round_tf32(v1));
                if (t == TT - 1) {
                    *(float2*)(h_out + (size_t)grow * 256 + c) = make_float2(v0, v1);
                } else {
                    float m0 = v0 * msk, m1 = v1 * msk;
                    hreg[rh][nt] = make_float2(m0, m1);
                    ht[row * HT_PITCH + c]     = round_tf32(m0);
                    ht[row * HT_PITCH + c + 1] = round_tf32(m1);
                }
            }
        }
        // next t's kt=0 barrier orders these writes vs ldmatrix reads
    }
}

// ---------------------------------------------------------------------------
// Heads
// ---------------------------------------------------------------------------
__global__ __launch_bounds__(256) void head_kernel(
    const float* __restrict__ t2a, const float* __restrict__ t2c,
    const float* __restrict__ Aw3, const float* __restrict__ Ab3,
    const float* __restrict__ Cw3, const float* __restrict__ Cb3,
    float* __restrict__ out)
{
    __shared__ float wa[12][256];
    __shared__ float wc[256];
    __shared__ float ba[12];
    __shared__ float bc;

    const int tid = threadIdx.x;
    for (int i = tid; i < 12 * 256; i += 256) wa[i >> 8][i & 255] = Aw3[i];
    if (tid < 256) wc[tid] = Cw3[tid];
    if (tid < 12)  ba[tid] = Ab3[tid];
    if (tid == 0)  bc = Cb3[0];
    __syncthreads();

    const int warp = tid >> 5;
    const int lane = tid & 31;
    const size_t row = (size_t)blockIdx.x * 8 + warp;

    const float* ra = t2a + row * 256;
    const float* rc = t2c + row * 256;
    float va[8], vc[8];
#pragma unroll
    for (int u = 0; u < 8; u++) {
        va[u] = ra[lane + 32 * u];
        vc[u] = rc[lane + 32 * u];
    }

    float s[13];
#pragma unroll
    for (int a = 0; a < 12; a++) {
        float acc = 0.f;
#pragma unroll
        for (int u = 0; u < 8; u++) acc = fmaf(va[u], wa[a][lane + 32 * u], acc);
        s[a] = acc;
    }
    {
        float acc = 0.f;
#pragma unroll
        for (int u = 0; u < 8; u++) acc = fmaf(vc[u], wc[lane + 32 * u], acc);
        s[12] = acc;
    }
#pragma unroll
    for (int a = 0; a < 13; a++)
#pragma unroll
        for (int o = 16; o > 0; o >>= 1)
            s[a] += __shfl_xor_sync(0xffffffffu, s[a], o);
    if (lane == 0) {
        float* o = out + row * 13;
#pragma unroll
        for (int a = 0; a < 12; a++) o[a] = s[a] + ba[a];
        o[12] = s[12] + bc;
    }
}

__global__ void std_kernel(const float* __restrict__ log_std, float* __restrict__ out)
{
    int a = threadIdx.x;
    if (a < AA) {
        float v = log_std[a];
        v = fminf(fmaxf(v, -2.0f), -0.5f);
        out[a] = __expf(v);
    }
}

// ---------------------------------------------------------------------------
extern "C" void kernel_launch(void* const* d_in, const int* in_sizes, int n_in,
                              void* d_out, int out_size)
{
    const float* features = (const float*)d_in[0];
    const float* hidden   = (const float*)d_in[1];
    const float* W_ih     = (const float*)d_in[2];
    const float* W_hh     = (const float*)d_in[3];
    const float* b_ih     = (const float*)d_in[4];
    const float* b_hh     = (const float*)d_in[5];
    const float* Aw1      = (const float*)d_in[6];
    const float* Ab1      = (const float*)d_in[7];
    const float* Aw2      = (const float*)d_in[8];
    const float* Ab2      = (const float*)d_in[9];
    const float* Aw3      = (const float*)d_in[10];
    const float* Ab3      = (const float*)d_in[11];
    const float* Cw1      = (const float*)d_in[12];
    const float* Cb1      = (const float*)d_in[13];
    const float* Cw2      = (const float*)d_in[14];
    const float* Cb2      = (const float*)d_in[15];
    const float* Cw3      = (const float*)d_in[16];
    const float* Cb3      = (const float*)d_in[17];
    const float* log_std  = (const float*)d_in[18];
    const int*   starts   = (const int*)d_in[19];

    float* out      = (float*)d_out;
    float* out_main = out;
    float* out_std  = out + (size_t)MTOT * 13;
    float* out_h    = out + (size_t)MTOT * 13 + AA;

    float *xg, *lat, *t1, *t2a, *t2c, *wt, *wihr, *w1c, *w2a, *w2c, *b1c;
    cudaGetSymbolAddress((void**)&xg,   g_xg);
    cudaGetSymbolAddress((void**)&lat,  g_lat);
    cudaGetSymbolAddress((void**)&t1,   g_t1);
    cudaGetSymbolAddress((void**)&t2a,  g_t2a);
    cudaGetSymbolAddress((void**)&t2c,  g_t2c);
    cudaGetSymbolAddress((void**)&wt,   g_wt);
    cudaGetSymbolAddress((void**)&wihr, g_wihr);
    cudaGetSymbolAddress((void**)&w1c,  g_w1c);
    cudaGetSymbolAddress((void**)&w2a,  g_w2a);
    cudaGetSymbolAddress((void**)&w2c,  g_w2c);
    cudaGetSymbolAddress((void**)&b1c,  g_b1c);

    cudaFuncSetAttribute(gemm_mma<false, false>,
                         cudaFuncAttributeMaxDynamicSharedMemorySize, GEMM_SMEM);
    cudaFuncSetAttribute(gemm_mma<true, true>,
                         cudaFuncAttributeMaxDynamicSharedMemorySize, GEMM_SMEM);
    cudaFuncSetAttribute(gemm_mma<true, false>,
                         cudaFuncAttributeMaxDynamicSharedMemorySize, GEMM_SMEM);
    cudaFuncSetAttribute(gru_mma,
                         cudaFuncAttributeMaxDynamicSharedMemorySize, GRU_SMEM);

    dim3 blk(256);

    // Launch order: gru_mma is launch #4 (ncu profiles the 4th launch).
    // 1) all weight prep
    prep_all<<<1216, blk>>>(
        (const float4*)W_ih, (const float4*)Aw1, (const float4*)Cw1,
        (const float4*)Aw2, (const float4*)Cw2,
        (const float4*)Ab1, (const float4*)Cb1, W_hh,
        (float4*)wihr, (float4*)w1c, (float4*)w2a, (float4*)w2c,
        (float4*)b1c, wt);
    // 2) features rounded
    round_copy4<<<((size_t)MTOT*256)/1024, blk>>>((const float4*)features, (float4*)t1);
    // 3) xg = features @ W_ih^T + b_ih
    gemm_mma<false, false><<<dim3(G3/GBN, MTOT/GBM), blk, GEMM_SMEM>>>(
        t1, wihr, b_ih, xg, G3, FF, FF);
    // 4) GRU scan -> lat (tf32-rounded), h_last      <-- profiled launch
    gru_mma<<<BB/RB2, dim3(512), GRU_SMEM>>>(xg, hidden, wt, b_hh, starts, lat, out_h);
    // 5) fused actor+critic layer1 (reuses g_xg as [M,512])
    gemm_mma<true, true><<<dim3(512/GBN, MTOT/GBM), blk, GEMM_SMEM>>>(
        lat, w1c, b1c, xg, 512, HH, HH);
    // 6,7) layer2 actor / critic
    gemm_mma<true, false><<<dim3(HH/GBN, MTOT/GBM), blk, GEMM_SMEM>>>(
        xg,       w2a, Ab2, t2a, HH, HH, 512);
    gemm_mma<true, false><<<dim3(HH/GBN, MTOT/GBM), blk, GEMM_SMEM>>>(
        xg + 256, w2c, Cb2, t2c, HH, HH, 512);
    // 8) heads
    head_kernel<<<MTOT/8, blk>>>(t2a, t2c, Aw3, Ab3, Cw3, Cb3, out_main);
    // 9) std
    std_kernel<<<1, 32>>>(log_std, out_std);
}

// round 8
// speedup vs baseline: 1.0594x; 1.0088x over previous
#include <cuda_runtime.h>
#include <math.h>
#include <stdint.h>

// Problem dims
#define BB 4096
#define TT 64
#define FF 256
#define HH 256
#define AA 12
#define MTOT (BB*TT)            // 262144 rows
#define G3  768

// Scratch (device globals; no cudaMalloc allowed)
__device__ float g_xg [(size_t)MTOT * G3];     // xg, later reused as t12 [M,512]
__device__ float g_lat[(size_t)MTOT * HH];
__device__ float g_t1 [(size_t)MTOT * HH];     // rounded features
__device__ float g_t2a[(size_t)MTOT * HH];
__device__ float g_t2c[(size_t)MTOT * HH];
__device__ float g_wt2[16 * 14336];            // W_hh fragment-major (padded slots)
__device__ float g_wihr[768 * 256];            // W_ih rounded
__device__ float g_w1c [512 * 256];            // [Aw1; Cw1] rounded
__device__ float g_w2a [256 * 256];
__device__ float g_w2c [256 * 256];
__device__ float g_b1c [512];                  // [Ab1 | Cb1]

__device__ __forceinline__ float round_tf32(float x) {
    uint32_t r;
    asm("cvt.rna.tf32.f32 %0, %1;" : "=r"(r) : "f"(x));
    return __uint_as_float(r);
}

__device__ __forceinline__ uint32_t smem_u32(const void* p) {
    uint32_t a;
    asm("{ .reg .u64 t; cvta.to.shared.u64 t, %1; cvt.u32.u64 %0, t; }"
        : "=r"(a) : "l"(p));
    return a;
}

__device__ __forceinline__ void cp16_cg(void* dst, const void* src) {
    asm volatile("cp.async.cg.shared.global [%0], [%1], 16;"
                 :: "r"(smem_u32(dst)), "l"(src) : "memory");
}
__device__ __forceinline__ void l2_prefetch(const void* p) {
    asm volatile("prefetch.global.L2 [%0];" :: "l"(p));
}
#define CP_COMMIT()  asm volatile("cp.async.commit_group;" ::: "memory")
#define CP_WAIT1()   asm volatile("cp.async.wait_group 1;" ::: "memory")
#define CP_WAITALL() asm volatile("cp.async.wait_all;" ::: "memory")

// ldmatrix fragment loaders (tf32 elements as b16 pairs; mapping == mma frags)
#define LDMX4(r0,r1,r2,r3,addr) \
    asm volatile("ldmatrix.sync.aligned.m8n8.x4.shared.b16 {%0,%1,%2,%3}, [%4];" \
                 : "=r"(r0),"=r"(r1),"=r"(r2),"=r"(r3) : "r"(addr))
#define LDMX2(r0,r1,addr) \
    asm volatile("ldmatrix.sync.aligned.m8n8.x2.shared.b16 {%0,%1}, [%2];" \
                 : "=r"(r0),"=r"(r1) : "r"(addr))

__device__ __forceinline__ void mma_tf32(
    float& c0, float& c1, float& c2, float& c3,
    uint32_t a0, uint32_t a1, uint32_t a2, uint32_t a3,
    uint32_t b0, uint32_t b1)
{
    asm volatile(
        "mma.sync.aligned.m16n8k8.row.col.f32.tf32.tf32.f32 "
        "{%0,%1,%2,%3}, {%4,%5,%6,%7}, {%8,%9}, {%0,%1,%2,%3};"
        : "+f"(c0), "+f"(c1), "+f"(c2), "+f"(c3)
        : "r"(a0), "r"(a1), "r"(a2), "r"(a3), "r"(b0), "r"(b1));
}

// ===========================================================================
// Prep: ALL weight prep in one kernel (keeps gru_mma at launch #4 for ncu).
// W_hh -> fragment-major layout:
//   element (gcol, k): g=gcol>>8, rem=gcol&255, wn=rem>>5, nt=(rem>>3)&3,
//   lanehi=rem&7; kt=k>>4, s=(k>>3)&1, lanelo=k&3, b=(k>>2)&1;
//   lane=lanehi*4+lanelo; j=g*4+nt; idx=j*2+b;
//   dst = (kt*2+s)*7168 + (wn*32+lane)*28 + idx
// ===========================================================================
#define PREP_F4 114688
__global__ void prep_all(
    const float4* __restrict__ Wih, const float4* __restrict__ Aw1,
    const float4* __restrict__ Cw1, const float4* __restrict__ Aw2,
    const float4* __restrict__ Cw2, const float4* __restrict__ Ab1,
    const float4* __restrict__ Cb1, const float*  __restrict__ W_hh,
    float4* __restrict__ wihr, float4* __restrict__ w1c,
    float4* __restrict__ w2a, float4* __restrict__ w2c,
    float4* __restrict__ b1c, float* __restrict__ Wt2)
{
    int i = blockIdx.x * 256 + threadIdx.x;
    if (i < PREP_F4) {
        const float4* src;
        float4* dst;
        if (i < 49152)      { src = Wih + i;            dst = wihr + i; }
        else if (i < 65536) { src = Aw1 + (i - 49152);  dst = w1c + (i - 49152); }
        else if (i < 81920) { src = Cw1 + (i - 65536);  dst = w1c + 16384 + (i - 65536); }
        else if (i < 98304) { src = Aw2 + (i - 81920);  dst = w2a + (i - 81920); }
        else                { src = Cw2 + (i - 98304);  dst = w2c + (i - 98304); }
        float4 v = *src;
        v.x = round_tf32(v.x); v.y = round_tf32(v.y);
        v.z = round_tf32(v.z); v.w = round_tf32(v.w);
        *dst = v;
        if (i < 64)       b1c[i] = Ab1[i];
        else if (i < 128) b1c[i] = Cb1[i - 64];
    } else {
        int j2 = i - PREP_F4;              // 0..196607
        int gcol = j2 >> 8, k = j2 & 255;
        int g = gcol >> 8, rem = gcol & 255;
        int wn = rem >> 5, nt = (rem >> 3) & 3, lanehi = rem & 7;
        int kt = k >> 4, s = (k >> 3) & 1, lanelo = k & 3, b = (k >> 2) & 1;
        int lane = lanehi * 4 + lanelo;
        int idx = (g * 4 + nt) * 2 + b;
        Wt2[(size_t)(kt * 2 + s) * 7168 + (wn * 32 + lane) * 28 + idx] =
            round_tf32(W_hh[(size_t)gcol * 256 + k]);
    }
}

__global__ void round_copy4(const float4* __restrict__ src, float4* __restrict__ dst)
{
    size_t i = (size_t)blockIdx.x * 256 + threadIdx.x;
    float4 v = src[i];
    v.x = round_tf32(v.x); v.y = round_tf32(v.y);
    v.z = round_tf32(v.z); v.w = round_tf32(v.w);
    dst[i] = v;
}

// ===========================================================================
// tf32 mma.sync GEMM, cp.async 2-stage, 2 CTAs/SM, ldmatrix fragments.
// (unchanged from R6/R7)
// ===========================================================================
#define GBM 128
#define GBN 128
#define GBK 32
#define APITCH 36
#define STAGEF (GBM * APITCH)                 // 4608 floats (A or B)
#define GEMM_SMEM ((4 * STAGEF + GBN) * 4)    // 74240 bytes -> 2 CTAs/SM

template<bool DO_TANH, bool ROUND_OUT>
__global__ __launch_bounds__(256, 2) void gemm_mma(
    const float* __restrict__ A, const float* __restrict__ W,
    const float* __restrict__ bias, float* __restrict__ C,
    int N, int K, int lda)
{
    extern __shared__ float sm[];
    float* sBias = sm + 4 * STAGEF;

    const int tid  = threadIdx.x;
    const int lane = tid & 31;
    const int wid  = tid >> 5;
    const int wm   = wid >> 2;
    const int wn   = wid & 3;
    const int    bn = blockIdx.x * GBN;
    const size_t bm = (size_t)blockIdx.y * GBM;

    if (tid < GBN) sBias[tid] = bias[bn + tid];

    const int lrow = tid >> 1;
    const int lkq  = (tid & 1) * 16;
    const float* Ag = A + (bm + lrow) * lda + lkq;
    const float* Wg = W + ((size_t)(bn + lrow)) * K + lkq;

    const uint32_t sbase = smem_u32(sm);
    const int a_lm = (wm * 64 + (lane & 15)) * APITCH + ((lane >> 4) << 2);
    const int b_lm = (wn * 32 + (lane & 7)) * APITCH + (((lane >> 3) & 1) << 2);

    float acc[4][4][4];
#pragma unroll
    for (int mt = 0; mt < 4; mt++)
#pragma unroll
        for (int nt = 0; nt < 4; nt++)
#pragma unroll
            for (int q = 0; q < 4; q++) acc[mt][nt][q] = 0.f;

    const int NK = K / GBK;

    auto stage_copy = [&](int kt) {
        float* st = sm + (kt & 1) * 2 * STAGEF;
        const float* ap = Ag + kt * GBK;
        const float* wp = Wg + kt * GBK;
        float* dA = st + lrow * APITCH + lkq;
        float* dB = st + STAGEF + lrow * APITCH + lkq;
#pragma unroll
        for (int u = 0; u < 4; u++) {
            cp16_cg(dA + 4 * u, ap + 4 * u);
            cp16_cg(dB + 4 * u, wp + 4 * u);
        }
    };

    stage_copy(0); CP_COMMIT();
    stage_copy(1); CP_COMMIT();

    for (int kt = 0; kt < NK; kt++) {
        if (kt < NK - 1) { CP_WAIT1(); } else { CP_WAITALL(); }
        __syncthreads();

        const uint32_t bufA = sbase + ((kt & 1) * 2 * STAGEF) * 4;
        const uint32_t bufB = bufA + STAGEF * 4;
#pragma unroll
        for (int k8 = 0; k8 < 4; k8++) {
            const int k0 = k8 * 8;
            uint32_t a[4][4];
#pragma unroll
            for (int mt = 0; mt < 4; mt++)
                LDMX4(a[mt][0], a[mt][1], a[mt][2], a[mt][3],
                      bufA + (a_lm + mt * 16 * APITCH + k0) * 4);
            uint32_t b[4][2];
#pragma unroll
            for (int nt = 0; nt < 4; nt++)
                LDMX2(b[nt][0], b[nt][1],
                      bufB + (b_lm + nt * 8 * APITCH + k0) * 4);
#pragma unroll
            for (int mt = 0; mt < 4; mt++)
#pragma unroll
                for (int nt = 0; nt < 4; nt++)
                    mma_tf32(acc[mt][nt][0], acc[mt][nt][1],
                             acc[mt][nt][2], acc[mt][nt][3],
                             a[mt][0], a[mt][1], a[mt][2], a[mt][3],
                             b[nt][0], b[nt][1]);
        }
        __syncthreads();
        if (kt + 2 < NK) { stage_copy(kt + 2); CP_COMMIT(); }
    }

#pragma unroll
    for (int mt = 0; mt < 4; mt++) {
        const size_t row = bm + wm * 64 + mt * 16 + (lane >> 2);
        float* c0p = C + row * N + bn + wn * 32;
        float* c1p = c0p + (size_t)8 * N;
#pragma unroll
        for (int nt = 0; nt < 4; nt++) {
            const int cc = nt * 8 + (lane & 3) * 2;
            const float bx = sBias[wn * 32 + cc];
            const float by = sBias[wn * 32 + cc + 1];
            float v0 = acc[mt][nt][0] + bx, v1 = acc[mt][nt][1] + by;
            float v2 = acc[mt][nt][2] + bx, v3 = acc[mt][nt][3] + by;
            if (DO_TANH) {
                v0 = tanhf(v0); v1 = tanhf(v1);
                v2 = tanhf(v2); v3 = tanhf(v3);
            }
            if (ROUND_OUT) {
                v0 = round_tf32(v0); v1 = round_tf32(v1);
                v2 = round_tf32(v2); v3 = round_tf32(v3);
            }
            *(float2*)(c0p + cc) = make_float2(v0, v1);
            *(float2*)(c1p + cc) = make_float2(v2, v3);
        }
    }
}

// ===========================================================================
// GRU scan: 512 threads (16 warps), fragment-major W (6xLDS.128 per s-step),
// fp32 h in registers, tf32 copy in smem for ldmatrix A.
// Continuous 3-stage cp.async W pipeline, 1 barrier/kt, xg L2 prefetch.
// ===========================================================================
#define RB2 32
#define HT_PITCH 260
#define WS_STAGE 14336            // floats per k-tile (2 s-steps x 7168)
// smem: ws[3][14336] | ht[32][260] | sst[32][64] | sbh[768]
#define GRU_SMEM ((3*WS_STAGE + 32*HT_PITCH + 768) * 4 + 32*64*4)   // 216576 B

__global__ __launch_bounds__(512, 1) void gru_mma(
    const float* __restrict__ xg, const float* __restrict__ h0,
    const float* __restrict__ Wt2, const float* __restrict__ b_hh,
    const int* __restrict__ starts,
    float* __restrict__ lat, float* __restrict__ h_out)
{
    extern __shared__ float sm[];
    float* ws  = sm;                          // [3][14336]
    float* ht  = ws + 3 * WS_STAGE;           // [32][260]
    int*   sst = (int*)(ht + 32 * HT_PITCH);  // [32][64]
    float* sbh = (float*)(sst + 32 * 64);     // [768]

    const int tid  = threadIdx.x;
    const int lane = tid & 31;
    const int w    = tid >> 5;      // 0..15
    const int wm   = w >> 3;        // 0..1: row half
    const int wn   = w & 7;         // 0..7: 32-col group
    const int b0   = blockIdx.x * RB2;

    for (int i = tid; i < 32 * 64; i += 512)
        sst[i] = starts[(size_t)(b0 + (i >> 6)) * TT + (i & 63)];
    for (int i = tid; i < 768; i += 512) sbh[i] = b_hh[i];

    // fp32 h in registers; tf32 copy in smem
    float2 hreg[2][4];
#pragma unroll
    for (int rh = 0; rh < 2; rh++) {
        const int row = wm * 16 + rh * 8 + (lane >> 2);
        const float m0 = starts[(size_t)(b0 + row) * TT] ? 0.f : 1.f;
#pragma unroll
        for (int nt = 0; nt < 4; nt++) {
            const int c = wn * 32 + nt * 8 + (lane & 3) * 2;
            float2 v = *(const float2*)(h0 + (size_t)(b0 + row) * 256 + c);
            v.x *= m0; v.y *= m0;
            hreg[rh][nt] = v;
            ht[row * HT_PITCH + c]     = round_tf32(v.x);
            ht[row * HT_PITCH + c + 1] = round_tf32(v.y);
        }
    }

    // W staging: linear copy, 7 float4 per thread per k-tile
    auto stageW = [&](int tile, int buf) {
        const float4* src = (const float4*)(Wt2 + (size_t)tile * WS_STAGE) + tid;
        float4* dst = (float4*)(ws + buf * WS_STAGE) + tid;
#pragma unroll
        for (int u = 0; u < 7; u++)
            cp16_cg(dst + u * 512, src + u * 512);
    };

    stageW(0, 0); CP_COMMIT();
    stageW(1, 1); CP_COMMIT();

    // ldmatrix A base (16x8 tf32 tile at rows wm*16..+16)
    const uint32_t ht_lm = smem_u32(ht)
        + ((wm * 16 + (lane & 15)) * HT_PITCH + ((lane >> 4) << 2)) * 4;

    // per-thread B fragment slot base (28 floats, conflict-free phases)
    const int bslot = (wn * 32 + lane) * 28;

    const int KS_TOTAL = TT * 16;     // 1024
    int ks = 0;

    for (int t = 0; t < TT; t++) {
        float acc[12][4];
#pragma unroll
        for (int j = 0; j < 12; j++)
#pragma unroll
            for (int q = 0; q < 4; q++) acc[j][q] = 0.f;

        for (int kt = 0; kt < 16; kt++) {
            if (ks < KS_TOTAL - 1) { CP_WAIT1(); } else { CP_WAITALL(); }
            __syncthreads();   // stage ks ready; kt==0 also orders ht writes

            if (ks + 2 < KS_TOTAL) {
                stageW((ks + 2) & 15, (ks + 2) % 3);
                CP_COMMIT();
            }

            if (tid < 48) {
                int li = kt * 48 + tid;
                int r = li / 24, cl = li % 24;
                l2_prefetch(xg + ((size_t)(b0 + r) * TT + t) * G3 + cl * 32);
            }

            const float* wstage = ws + (ks % 3) * WS_STAGE;
#pragma unroll
            for (int s = 0; s < 2; s++) {
                const int kg = kt * 16 + s * 8;
                uint32_t a0, a1, a2, a3;
                LDMX4(a0, a1, a2, a3, ht_lm + kg * 4);
                const float* wb = wstage + s * 7168 + bslot;
                float4 bf[6];
#pragma unroll
                for (int u = 0; u < 6; u++)
                    bf[u] = *(const float4*)(wb + u * 4);
                const uint32_t* bw = (const uint32_t*)bf;
#pragma unroll
                for (int j = 0; j < 12; j++)
                    mma_tf32(acc[j][0], acc[j][1], acc[j][2], acc[j][3],
                             a0, a1, a2, a3, bw[j * 2], bw[j * 2 + 1]);
            }
            ks++;
        }
        __syncthreads();   // mma reads of ht done before pointwise writes

        // pointwise GRU update (h fp32 in registers)
#pragma unroll
        for (int rh = 0; rh < 2; rh++) {
            const int row  = wm * 16 + rh * 8 + (lane >> 2);
            const int grow = b0 + row;
            const size_t gbt = (size_t)grow * TT + t;
            const float* xb = xg + gbt * 768;
            float* lb = lat + gbt * 256;
            float msk = 1.f;
            if (t < TT - 1) msk = sst[row * 64 + t + 1] ? 0.f : 1.f;
            const int q = rh * 2;
#pragma unroll
            for (int nt = 0; nt < 4; nt++) {
                const int c = wn * 32 + nt * 8 + (lane & 3) * 2;
                float2 xr = *(const float2*)(xb + c);
                float2 xz = *(const float2*)(xb + 256 + c);
                float2 xn = *(const float2*)(xb + 512 + c);
                float hr0 = acc[nt][q]         + sbh[c];
                float hr1 = acc[nt][q + 1]     + sbh[c + 1];
                float hz0 = acc[4 + nt][q]     + sbh[256 + c];
                float hz1 = acc[4 + nt][q + 1] + sbh[256 + c + 1];
                float hn0 = acc[8 + nt][q]     + sbh[512 + c];
                float hn1 = acc[8 + nt][q + 1] + sbh[512 + c + 1];
                float r0 = 1.f / (1.f + __expf(-(xr.x + hr0)));
                float r1 = 1.f / (1.f + __expf(-(xr.y + hr1)));
                float z0 = 1.f / (1.f + __expf(-(xz.x + hz0)));
                float z1 = 1.f / (1.f + __expf(-(xz.y + hz1)));
                float n0 = tanhf(xn.x + r0 * hn0);
                float n1 = tanhf(xn.y + r1 * hn1);
                float v0 = (1.f - z0) * n0 + z0 * hreg[rh][nt].x;
                float v1 = (1.f - z1) * n1 + z1 * hreg[rh][nt].y;
                *(float2*)(lb + c) = make_float2(round_tf32(v0), round_tf32(v1));
                if (t == TT - 1) {
                    *(float2*)(h_out + (size_t)grow * 256 + c) = make_float2(v0, v1);
                } else {
                    float m0 = v0 * msk, m1 = v1 * msk;
                    hreg[rh][nt] = make_float2(m0, m1);
                    ht[row * HT_PITCH + c]     = round_tf32(m0);
                    ht[row * HT_PITCH + c + 1] = round_tf32(m1);
                }
            }
        }
        // next t's kt=0 barrier orders these writes vs ldmatrix reads
    }
}

// ---------------------------------------------------------------------------
// Heads
// ---------------------------------------------------------------------------
__global__ __launch_bounds__(256) void head_kernel(
    const float* __restrict__ t2a, const float* __restrict__ t2c,
    const float* __restrict__ Aw3, const float* __restrict__ Ab3,
    const float* __restrict__ Cw3, const float* __restrict__ Cb3,
    float* __restrict__ out)
{
    __shared__ float wa[12][256];
    __shared__ float wc[256];
    __shared__ float ba[12];
    __shared__ float bc;

    const int tid = threadIdx.x;
    for (int i = tid; i < 12 * 256; i += 256) wa[i >> 8][i & 255] = Aw3[i];
    if (tid < 256) wc[tid] = Cw3[tid];
    if (tid < 12)  ba[tid] = Ab3[tid];
    if (tid == 0)  bc = Cb3[0];
    __syncthreads();

    const int warp = tid >> 5;
    const int lane = tid & 31;
    const size_t row = (size_t)blockIdx.x * 8 + warp;

    const float* ra = t2a + row * 256;
    const float* rc = t2c + row * 256;
    float va[8], vc[8];
#pragma unroll
    for (int u = 0; u < 8; u++) {
        va[u] = ra[lane + 32 * u];
        vc[u] = rc[lane + 32 * u];
    }

    float s[13];
#pragma unroll
    for (int a = 0; a < 12; a++) {
        float acc = 0.f;
#pragma unroll
        for (int u = 0; u < 8; u++) acc = fmaf(va[u], wa[a][lane + 32 * u], acc);
        s[a] = acc;
    }
    {
        float acc = 0.f;
#pragma unroll
        for (int u = 0; u < 8; u++) acc = fmaf(vc[u], wc[lane + 32 * u], acc);
        s[12] = acc;
    }
#pragma unroll
    for (int a = 0; a < 13; a++)
#pragma unroll
        for (int o = 16; o > 0; o >>= 1)
            s[a] += __shfl_xor_sync(0xffffffffu, s[a], o);
    if (lane == 0) {
        float* o = out + row * 13;
#pragma unroll
        for (int a = 0; a < 12; a++) o[a] = s[a] + ba[a];
        o[12] = s[12] + bc;
    }
}

__global__ void std_kernel(const float* __restrict__ log_std, float* __restrict__ out)
{
    int a = threadIdx.x;
    if (a < AA) {
        float v = log_std[a];
        v = fminf(fmaxf(v, -2.0f), -0.5f);
        out[a] = __expf(v);
    }
}

// ---------------------------------------------------------------------------
extern "C" void kernel_launch(void* const* d_in, const int* in_sizes, int n_in,
                              void* d_out, int out_size)
{
    const float* features = (const float*)d_in[0];
    const float* hidden   = (const float*)d_in[1];
    const float* W_ih     = (const float*)d_in[2];
    const float* W_hh     = (const float*)d_in[3];
    const float* b_ih     = (const float*)d_in[4];
    const float* b_hh     = (const float*)d_in[5];
    const float* Aw1      = (const float*)d_in[6];
    const float* Ab1      = (const float*)d_in[7];
    const float* Aw2      = (const float*)d_in[8];
    const float* Ab2      = (const float*)d_in[9];
    const float* Aw3      = (const float*)d_in[10];
    const float* Ab3      = (const float*)d_in[11];
    const float* Cw1      = (const float*)d_in[12];
    const float* Cb1      = (const float*)d_in[13];
    const float* Cw2      = (const float*)d_in[14];
    const float* Cb2      = (const float*)d_in[15];
    const float* Cw3      = (const float*)d_in[16];
    const float* Cb3      = (const float*)d_in[17];
    const float* log_std  = (const float*)d_in[18];
    const int*   starts   = (const int*)d_in[19];

    float* out      = (float*)d_out;
    float* out_main = out;
    float* out_std  = out + (size_t)MTOT * 13;
    float* out_h    = out + (size_t)MTOT * 13 + AA;

    float *xg, *lat, *t1, *t2a, *t2c, *wt2, *wihr, *w1c, *w2a, *w2c, *b1c;
    cudaGetSymbolAddress((void**)&xg,   g_xg);
    cudaGetSymbolAddress((void**)&lat,  g_lat);
    cudaGetSymbolAddress((void**)&t1,   g_t1);
    cudaGetSymbolAddress((void**)&t2a,  g_t2a);
    cudaGetSymbolAddress((void**)&t2c,  g_t2c);
    cudaGetSymbolAddress((void**)&wt2,  g_wt2);
    cudaGetSymbolAddress((void**)&wihr, g_wihr);
    cudaGetSymbolAddress((void**)&w1c,  g_w1c);
    cudaGetSymbolAddress((void**)&w2a,  g_w2a);
    cudaGetSymbolAddress((void**)&w2c,  g_w2c);
    cudaGetSymbolAddress((void**)&b1c,  g_b1c);

    cudaFuncSetAttribute(gemm_mma<false, false>,
                         cudaFuncAttributeMaxDynamicSharedMemorySize, GEMM_SMEM);
    cudaFuncSetAttribute(gemm_mma<true, true>,
                         cudaFuncAttributeMaxDynamicSharedMemorySize, GEMM_SMEM);
    cudaFuncSetAttribute(gemm_mma<true, false>,
                         cudaFuncAttributeMaxDynamicSharedMemorySize, GEMM_SMEM);
    cudaFuncSetAttribute(gru_mma,
                         cudaFuncAttributeMaxDynamicSharedMemorySize, GRU_SMEM);

    dim3 blk(256);

    // Launch order: gru_mma is launch #4 (ncu profiles the 4th launch).
    // 1) all weight prep (round + W_hh fragment-major permute + bias concat)
    prep_all<<<1216, blk>>>(
        (const float4*)W_ih, (const float4*)Aw1, (const float4*)Cw1,
        (const float4*)Aw2, (const float4*)Cw2,
        (const float4*)Ab1, (const float4*)Cb1, W_hh,
        (float4*)wihr, (float4*)w1c, (float4*)w2a, (float4*)w2c,
        (float4*)b1c, wt2);
    // 2) features rounded
    round_copy4<<<((size_t)MTOT*256)/1024, blk>>>((const float4*)features, (float4*)t1);
    // 3) xg = features @ W_ih^T + b_ih
    gemm_mma<false, false><<<dim3(G3/GBN, MTOT/GBM), blk, GEMM_SMEM>>>(
        t1, wihr, b_ih, xg, G3, FF, FF);
    // 4) GRU scan -> lat (tf32-rounded), h_last      <-- profiled launch
    gru_mma<<<BB/RB2, dim3(512), GRU_SMEM>>>(xg, hidden, wt2, b_hh, starts, lat, out_h);
    // 5) fused actor+critic layer1 (reuses g_xg as [M,512])
    gemm_mma<true, true><<<dim3(512/GBN, MTOT/GBM), blk, GEMM_SMEM>>>(
        lat, w1c, b1c, xg, 512, HH, HH);
    // 6,7) layer2 actor / critic
    gemm_mma<true, false><<<dim3(HH/GBN, MTOT/GBM), blk, GEMM_SMEM>>>(
        xg,       w2a, Ab2, t2a, HH, HH, 512);
    gemm_mma<true, false><<<dim3(HH/GBN, MTOT/GBM), blk, GEMM_SMEM>>>(
        xg + 256, w2c, Cb2, t2c, HH, HH, 512);
    // 8) heads
    head_kernel<<<MTOT/8, blk>>>(t2a, t2c, Aw3, Ab3, Cw3, Cb3, out_main);
    // 9) std
    std_kernel<<<1, 32>>>(log_std, out_std);
}